// round 10
// baseline (speedup 1.0000x reference)
#include <cuda_runtime.h>
#include <cuda_bf16.h>
#include <cuda_fp16.h>
#include <cstdint>
#include <math.h>

#define BB 64
#define TT 39
#define MAXLEN 40
#define FF 1024
#define EE 300
#define HH 512
#define G4 2048
#define VV 32000
#define XDIM 1324
#define MPAD 2560  // padded A rows for the MMA

// ---------------- scratch (static device globals; no runtime alloc) ----------------
__device__ float g_lt[BB * FF];
__device__ int   g_si[BB];
__device__ int   g_dl[BB];
__device__ int   g_caps[BB * MAXLEN];
__device__ int   g_Mact;
__device__ int   g_act_src[TT * BB];
__device__ int   g_act_dst[TT * BB];
__device__ float g_base[BB * G4];
__device__ float g_Aemb[TT * BB * EE];
__device__ float g_gatepre[(size_t)TT * BB * G4];
__device__ float g_hall[(size_t)TT * BB * HH];
__device__ float g_c[BB * HH];
__device__ float g_Wq[HH * HH * 4];
// fp16 operands for the tensor-core vocab GEMM (A 2-limb, B single)
__device__ __half g_Bf[(size_t)VV * HH];
__device__ __half g_Ah[(size_t)MPAD * HH];
__device__ __half g_Al[(size_t)MPAD * HH];

// ---------------- f32x2 helpers ----------------
#define FFMA2(acc, a, b) asm("fma.rn.f32x2 %0, %1, %2, %0;" : "+l"(acc) : "l"(a), "l"(b))
__device__ __forceinline__ unsigned long long PACK2(float x) {
    unsigned long long r;
    asm("mov.b64 %0, {%1, %1};" : "=l"(r) : "f"(x));
    return r;
}
__device__ __forceinline__ unsigned long long PACKF2(float lo, float hi) {
    unsigned long long r;
    asm("mov.b64 %0, {%1, %2};" : "=l"(r) : "f"(lo), "f"(hi));
    return r;
}
#define UNPACK2(lo, hi, v) asm("mov.b64 {%0, %1}, %2;" : "=f"(lo), "=f"(hi) : "l"(v))

// ---------------- baseline-PTX tensor helpers (valid on plain sm_103) ----------------
__device__ __forceinline__ uint32_t s2u(const void* p) {
    uint32_t a;
    asm("{ .reg .u64 t; cvta.to.shared.u64 t, %1; cvt.u32.u64 %0, t; }" : "=r"(a) : "l"(p));
    return a;
}

#define LDSM4(R, addr)                                                        \
    asm volatile("ldmatrix.sync.aligned.m8n8.x4.shared.b16 {%0,%1,%2,%3}, [%4];" \
                 : "=r"((R)[0]), "=r"((R)[1]), "=r"((R)[2]), "=r"((R)[3])     \
                 : "r"(addr))

#define MMA16816F(C, A, B0, B1)                                               \
    asm volatile(                                                             \
        "mma.sync.aligned.m16n8k16.row.col.f32.f16.f16.f32 "                  \
        "{%0,%1,%2,%3}, {%4,%5,%6,%7}, {%8,%9}, {%0,%1,%2,%3};"               \
        : "+f"((C)[0]), "+f"((C)[1]), "+f"((C)[2]), "+f"((C)[3])              \
        : "r"((A)[0]), "r"((A)[1]), "r"((A)[2]), "r"((A)[3]), "r"(B0), "r"(B1))

// ---------------- setup: sort, caps gather, compaction, aux outputs ----------------
__global__ void setup_kernel(const int* __restrict__ enc, const int* __restrict__ capl,
                             float* __restrict__ out) {
    __shared__ int len[BB];
    __shared__ int si[BB];
    int t = threadIdx.x;  // 64 threads
    if (t < BB) len[t] = capl[t];
    __syncthreads();
    if (t < BB) {
        int L = len[t];
        int r = 0;
        for (int j = 0; j < BB; ++j) {
            int Lj = len[j];
            if (Lj > L || (Lj == L && j < t)) r++;
        }
        si[r] = t;  // stable descending argsort
    }
    __syncthreads();
    const size_t OFF = (size_t)TT * BB * VV;
    if (t < BB) {
        int bsrc = si[t];
        g_si[t] = bsrc;
        int dl = len[bsrc] - 1;
        g_dl[t] = dl;
        for (int w = 0; w < MAXLEN; ++w) {
            int c = enc[bsrc * MAXLEN + w];
            g_caps[t * MAXLEN + w] = c;
            out[OFF + t * MAXLEN + w] = (float)c;
        }
        out[OFF + BB * MAXLEN + t] = (float)dl;
        out[OFF + BB * MAXLEN + BB + t] = (float)bsrc;
    }
    __syncthreads();
    if (t == 0) {
        int m = 0;
        for (int tt = 0; tt < TT; ++tt)
            for (int b = 0; b < BB; ++b)
                if (tt < g_dl[b]) {
                    g_act_src[m] = tt * BB + b;
                    g_act_dst[m] = b * TT + tt;
                    m++;
                }
        g_Mact = m;
        for (int i = m; i < TT * BB; ++i) { g_act_src[i] = 0; g_act_dst[i] = 0; }
    }
}

// lt_sorted[r] = sum_s l_total[s, sort_ind[r], :]
__global__ void lt_kernel(const float* __restrict__ l_total) {
    int r = blockIdx.x;
    int bsrc = g_si[r];
    for (int f = threadIdx.x; f < FF; f += blockDim.x) {
        float s = l_total[(size_t)0 * BB * FF + bsrc * FF + f]
                + l_total[(size_t)1 * BB * FF + bsrc * FF + f]
                + l_total[(size_t)2 * BB * FF + bsrc * FF + f];
        g_lt[r * FF + f] = s;
    }
}

// Wq[(j*512 + k)*4 + g] = W_hh[(g*512 + j)*512 + k]
__global__ void wq_kernel(const float* __restrict__ W_hh) {
    int idx = blockIdx.x * blockDim.x + threadIdx.x;
    if (idx < HH * HH * 4) {
        int g = idx & 3;
        int k = (idx >> 2) & (HH - 1);
        int j = idx >> 11;
        g_Wq[idx] = W_hh[(size_t)(g * HH + j) * HH + k];
    }
}

// gather embedding rows for all (t,b)
__global__ void emb_gather(const float* __restrict__ emb_w) {
    int idx = blockIdx.x * blockDim.x + threadIdx.x;
    const int total = TT * BB * EE;
    if (idx < total) {
        int m = idx / EE;
        int k = idx - m * EE;
        int tt = m >> 6;
        int b = m & 63;
        int tok = g_caps[b * MAXLEN + tt];
        g_Aemb[idx] = emb_w[(size_t)tok * EE + k];
    }
}

// ---------------- fp16 conversions ----------------
__global__ void conv_wdc(const float* __restrict__ W) {
    int i4 = blockIdx.x * blockDim.x + threadIdx.x;
    if (i4 < VV * HH / 4) {
        float4 v = ((const float4*)W)[i4];
        __half2 p0 = __floats2half2_rn(v.x, v.y);
        __half2 p1 = __floats2half2_rn(v.z, v.w);
        reinterpret_cast<__half2*>(g_Bf)[i4 * 2 + 0] = p0;
        reinterpret_cast<__half2*>(g_Bf)[i4 * 2 + 1] = p1;
    }
}

__global__ void conv_hid() {
    int i4 = blockIdx.x * blockDim.x + threadIdx.x;
    if (i4 < MPAD * HH / 4) {
        int m = i4 >> 7;
        int k4 = i4 & 127;
        int Mact = g_Mact;
        int src = g_act_src[m < Mact ? m : (Mact - 1)];
        float4 v = *(const float4*)(g_hall + (size_t)src * HH + (k4 << 2));
        __half h0 = __float2half_rn(v.x);
        __half h1 = __float2half_rn(v.y);
        __half h2 = __float2half_rn(v.z);
        __half h3 = __float2half_rn(v.w);
        __half l0 = __float2half_rn(v.x - __half2float(h0));
        __half l1 = __float2half_rn(v.y - __half2float(h1));
        __half l2 = __float2half_rn(v.z - __half2float(h2));
        __half l3 = __float2half_rn(v.w - __half2float(h3));
        __half2* Ah2 = reinterpret_cast<__half2*>(g_Ah);
        __half2* Al2 = reinterpret_cast<__half2*>(g_Al);
        Ah2[i4 * 2 + 0] = __halves2half2(h0, h1);
        Ah2[i4 * 2 + 1] = __halves2half2(h2, h3);
        Al2[i4 * 2 + 0] = __halves2half2(l0, l1);
        Al2[i4 * 2 + 1] = __halves2half2(l2, l3);
    }
}

// ---------------- SIMT SGEMM for the small pre-GEMMs (modes 0/1) ----------------
template <int MODE>
__global__ void __launch_bounds__(256, 2)
gemm_kernel(const float* __restrict__ Bm, const float* __restrict__ bias1,
            const float* __restrict__ bias2, float* __restrict__ Cout) {
    constexpr int K   = (MODE == 0) ? 1024 : 300;
    constexpr int LDA = (MODE == 0) ? 1024 : 300;
    constexpr int LDB = XDIM;
    constexpr int BC0 = (MODE == 0) ? 300 : 0;

    const float* A = (MODE == 0) ? g_lt : g_Aemb;
    int M_eff = (MODE == 0) ? 64 : (TT * BB);

    int m0 = blockIdx.y * 128;
    int n0 = blockIdx.x * 128;
    if (m0 >= M_eff) return;

    __shared__ float As[8][128];
    __shared__ float Bs[8][128];

    int tid = threadIdx.x;
    int lrow = tid & 127;
    int kq = (tid >> 7) << 2;
    int tx = tid & 15;
    int ty = tid >> 4;

    int am = min(m0 + lrow, M_eff - 1);
    const float* Ap = A + (size_t)am * LDA;
    const float* Bp = Bm + (size_t)(n0 + lrow) * LDB + BC0;

    unsigned long long acc[8][4];
#pragma unroll
    for (int i = 0; i < 8; ++i)
#pragma unroll
        for (int p = 0; p < 4; ++p) acc[i][p] = 0ull;

    const int nkt = (K + 7) >> 3;
    for (int kt = 0; kt < nkt; ++kt) {
        int kk = (kt << 3) + kq;
        float4 av, bv;
        if (kk + 3 < K) {
            av = *(const float4*)(Ap + kk);
            bv = *(const float4*)(Bp + kk);
        } else {
            av.x = (kk + 0 < K) ? Ap[kk + 0] : 0.f;
            av.y = (kk + 1 < K) ? Ap[kk + 1] : 0.f;
            av.z = (kk + 2 < K) ? Ap[kk + 2] : 0.f;
            av.w = (kk + 3 < K) ? Ap[kk + 3] : 0.f;
            bv.x = (kk + 0 < K) ? Bp[kk + 0] : 0.f;
            bv.y = (kk + 1 < K) ? Bp[kk + 1] : 0.f;
            bv.z = (kk + 2 < K) ? Bp[kk + 2] : 0.f;
            bv.w = (kk + 3 < K) ? Bp[kk + 3] : 0.f;
        }
        __syncthreads();
        As[kq + 0][lrow] = av.x; As[kq + 1][lrow] = av.y;
        As[kq + 2][lrow] = av.z; As[kq + 3][lrow] = av.w;
        Bs[kq + 0][lrow] = bv.x; Bs[kq + 1][lrow] = bv.y;
        Bs[kq + 2][lrow] = bv.z; Bs[kq + 3][lrow] = bv.w;
        __syncthreads();
#pragma unroll
        for (int k = 0; k < 8; ++k) {
            float4 a0 = *(const float4*)&As[k][ty * 8];
            float4 a1 = *(const float4*)&As[k][ty * 8 + 4];
            ulonglong2 b0 = *(const ulonglong2*)&Bs[k][tx * 8];
            ulonglong2 b1 = *(const ulonglong2*)&Bs[k][tx * 8 + 4];
            float amv[8] = {a0.x, a0.y, a0.z, a0.w, a1.x, a1.y, a1.z, a1.w};
#pragma unroll
            for (int i = 0; i < 8; ++i) {
                unsigned long long ap = PACK2(amv[i]);
                FFMA2(acc[i][0], ap, b0.x);
                FFMA2(acc[i][1], ap, b0.y);
                FFMA2(acc[i][2], ap, b1.x);
                FFMA2(acc[i][3], ap, b1.y);
            }
        }
    }

#pragma unroll
    for (int i = 0; i < 8; ++i) {
        int m = m0 + ty * 8 + i;
        if (m >= M_eff) continue;
#pragma unroll
        for (int p = 0; p < 4; ++p) {
            float lo, hi;
            UNPACK2(lo, hi, acc[i][p]);
            int n = n0 + tx * 8 + p * 2;
            if (MODE == 0) {
                g_base[(size_t)m * G4 + n + 0] = lo + bias1[n + 0] + bias2[n + 0];
                g_base[(size_t)m * G4 + n + 1] = hi + bias1[n + 1] + bias2[n + 1];
            } else {
                int b = m & 63;
                g_gatepre[(size_t)m * G4 + n + 0] = lo + g_base[(size_t)b * G4 + n + 0];
                g_gatepre[(size_t)m * G4 + n + 1] = hi + g_base[(size_t)b * G4 + n + 1];
            }
        }
    }
}

// ---------------- LSTM recurrence step ----------------
__global__ void lstm_step(int t) {
    extern __shared__ float hs[];  // [512][65] padded
    int tid = threadIdx.x;         // 512
    int b = tid & 63;
    int jj = tid >> 6;
    int j = blockIdx.x * 8 + jj;

    if (t > 0) {
        const float* hp = g_hall + (size_t)(t - 1) * BB * HH;
        for (int i = tid; i < BB * HH; i += 512) {
            int bb = i >> 9;
            int k = i & 511;
            hs[k * 65 + bb] = hp[i];
        }
        __syncthreads();
    }

    const float* gp = g_gatepre + ((size_t)t * BB + b) * G4 + j;
    float a0 = gp[0], a1 = gp[HH], a2 = gp[2 * HH], a3 = gp[3 * HH];

    if (t > 0) {
        unsigned long long accA = PACKF2(a0, a1);
        unsigned long long accB = PACKF2(a2, a3);
        const ulonglong2* W2 = (const ulonglong2*)(g_Wq + (size_t)j * HH * 4);
#pragma unroll 8
        for (int k = 0; k < HH; ++k) {
            unsigned long long hp2 = PACK2(hs[k * 65 + b]);
            ulonglong2 w = W2[k];
            FFMA2(accA, hp2, w.x);
            FFMA2(accB, hp2, w.y);
        }
        UNPACK2(a0, a1, accA);
        UNPACK2(a2, a3, accB);
    }

    float iv = 1.f / (1.f + expf(-a0));
    float fv = 1.f / (1.f + expf(-a1));
    float gv = tanhf(a2);
    float ov = 1.f / (1.f + expf(-a3));
    float cprev = (t > 0) ? g_c[b * HH + j] : 0.f;
    float c = fv * cprev + iv * gv;
    g_c[b * HH + j] = c;
    float h = ov * tanhf(c);
    g_hall[((size_t)t * BB + b) * HH + j] = h;
}

// zero masked prediction rows
__global__ void zerofill(float* __restrict__ out) {
    int tt = blockIdx.x;
    int b = blockIdx.y;
    if (tt < g_dl[b]) return;
    float4* p = (float4*)(out + ((size_t)b * TT + tt) * VV);
    float4 z = make_float4(0.f, 0.f, 0.f, 0.f);
    for (int i = threadIdx.x; i < VV / 4; i += blockDim.x) p[i] = z;
}

// ---------------- mma.sync fp16 2-term vocab GEMM ----------------
// C[m,n] = sum_k A[m,k]*B[n,k] ≈ Ah·Bf + Al·Bf  (fp32 accum; B fp16-rounded)
// CTA tile 128x128, 8 warps (4m x 2n), warp tile 32x64, k-chunks of 32.
// Smem row stride 80B (5*16B): 5r mod 8 is a permutation -> conflict-free ldmatrix.
#define VSTRIDE 80
#define OP_BYTES (128 * VSTRIDE)   // 10240
#define SMEM_VOC (3 * OP_BYTES)    // 30720

__global__ void __launch_bounds__(256, 2)
mma_vocab(const float* __restrict__ bias, float* __restrict__ out) {
    int Mact = g_Mact;
    int m0 = blockIdx.y << 7;
    if (m0 >= Mact) return;
    int n0 = blockIdx.x << 7;

    extern __shared__ char smem[];
    const uint32_t sb = s2u(smem);
    const uint32_t sAh = sb;
    const uint32_t sAl = sb + OP_BYTES;
    const uint32_t sBf = sb + 2 * OP_BYTES;

    int tid = threadIdx.x;
    int warp = tid >> 5;
    int lane = tid & 31;
    int wm = warp >> 1;  // 0..3
    int wn = warp & 1;   // 0..1

    float c[2][8][4];
#pragma unroll
    for (int mf = 0; mf < 2; ++mf)
#pragma unroll
        for (int nf = 0; nf < 8; ++nf)
#pragma unroll
            for (int q = 0; q < 4; ++q) c[mf][nf][q] = 0.f;

    // per-thread load slots: 2 x 16B units per operand per chunk
    int u0 = tid * 2;
    int lr0 = u0 >> 2, lc0 = u0 & 3;
    int lr1 = (u0 + 1) >> 2, lc1 = (u0 + 1) & 3;
    uint32_t so0 = (uint32_t)(lr0 * VSTRIDE + lc0 * 16);
    uint32_t so1 = (uint32_t)(lr1 * VSTRIDE + lc1 * 16);

    uint32_t a_off[2], b_off[4];
#pragma unroll
    for (int mf = 0; mf < 2; ++mf)
        a_off[mf] = (uint32_t)((wm * 32 + mf * 16 + (lane & 15)) * VSTRIDE + ((lane >> 4) << 4));
#pragma unroll
    for (int g = 0; g < 4; ++g)
        b_off[g] = (uint32_t)((wn * 64 + g * 16 + (lane & 15)) * VSTRIDE + ((lane >> 4) << 4));

#pragma unroll 1
    for (int ch = 0; ch < 16; ++ch) {
        int col0 = ch * 32;
        __syncthreads();
        {
            const __half* pAh = g_Ah + (size_t)m0 * HH + col0;
            const __half* pAl = g_Al + (size_t)m0 * HH + col0;
            const __half* pBf = g_Bf + (size_t)n0 * HH + col0;
            uint4 vah0 = *(const uint4*)(pAh + (size_t)lr0 * HH + lc0 * 8);
            uint4 vah1 = *(const uint4*)(pAh + (size_t)lr1 * HH + lc1 * 8);
            uint4 val0 = *(const uint4*)(pAl + (size_t)lr0 * HH + lc0 * 8);
            uint4 val1 = *(const uint4*)(pAl + (size_t)lr1 * HH + lc1 * 8);
            uint4 vbf0 = *(const uint4*)(pBf + (size_t)lr0 * HH + lc0 * 8);
            uint4 vbf1 = *(const uint4*)(pBf + (size_t)lr1 * HH + lc1 * 8);
            *(uint4*)(smem + (sAh - sb) + so0) = vah0;
            *(uint4*)(smem + (sAh - sb) + so1) = vah1;
            *(uint4*)(smem + (sAl - sb) + so0) = val0;
            *(uint4*)(smem + (sAl - sb) + so1) = val1;
            *(uint4*)(smem + (sBf - sb) + so0) = vbf0;
            *(uint4*)(smem + (sBf - sb) + so1) = vbf1;
        }
        __syncthreads();

#pragma unroll
        for (int ks = 0; ks < 2; ++ks) {
            uint32_t koff = (uint32_t)(ks * 32);
            uint32_t ah[2][4], al[2][4];
#pragma unroll
            for (int mf = 0; mf < 2; ++mf) {
                LDSM4(ah[mf], sAh + a_off[mf] + koff);
                LDSM4(al[mf], sAl + a_off[mf] + koff);
            }
#pragma unroll
            for (int g = 0; g < 4; ++g) {
                uint32_t bf[4];
                LDSM4(bf, sBf + b_off[g] + koff);
                // x4 frag order: r0 = n0-7/k0-7, r1 = n8-15/k0-7, r2 = n0-7/k8-15, r3 = n8-15/k8-15
#pragma unroll
                for (int mf = 0; mf < 2; ++mf) {
                    MMA16816F(c[mf][2 * g + 0], ah[mf], bf[0], bf[2]);  // Ah*B
                    MMA16816F(c[mf][2 * g + 0], al[mf], bf[0], bf[2]);  // Al*B
                    MMA16816F(c[mf][2 * g + 1], ah[mf], bf[1], bf[3]);
                    MMA16816F(c[mf][2 * g + 1], al[mf], bf[1], bf[3]);
                }
            }
        }
    }

    // epilogue: frag (mf,nf): c0,c1 -> row tq, cols 2*tr+{0,1}; c2,c3 -> row tq+8
    int tq = lane >> 2;
    int tr = lane & 3;
#pragma unroll
    for (int mf = 0; mf < 2; ++mf) {
#pragma unroll
        for (int half = 0; half < 2; ++half) {
            int m = m0 + wm * 32 + mf * 16 + half * 8 + tq;
            if (m >= Mact) continue;
            size_t dst = (size_t)g_act_dst[m] * VV;
#pragma unroll
            for (int nf = 0; nf < 8; ++nf) {
                int n = n0 + wn * 64 + nf * 8 + tr * 2;
                float2 v;
                v.x = c[mf][nf][half * 2 + 0] + bias[n + 0];
                v.y = c[mf][nf][half * 2 + 1] + bias[n + 1];
                *(float2*)(out + dst + n) = v;
            }
        }
    }
}

// ---------------- launch ----------------
extern "C" void kernel_launch(void* const* d_in, const int* in_sizes, int n_in,
                              void* d_out, int out_size) {
    const float* l_total = (const float*)d_in[0];
    const int*   enc     = (const int*)d_in[1];
    const int*   capl    = (const int*)d_in[2];
    const float* emb_w   = (const float*)d_in[3];
    const float* W_ih    = (const float*)d_in[4];
    const float* W_hh    = (const float*)d_in[5];
    const float* b_ih    = (const float*)d_in[6];
    const float* b_hh    = (const float*)d_in[7];
    const float* wdc_W   = (const float*)d_in[8];
    const float* wdc_b   = (const float*)d_in[9];
    float* out = (float*)d_out;

    cudaFuncSetAttribute(lstm_step, cudaFuncAttributeMaxDynamicSharedMemorySize, 512 * 65 * 4);
    cudaFuncSetAttribute(mma_vocab, cudaFuncAttributeMaxDynamicSharedMemorySize, SMEM_VOC);

    setup_kernel<<<1, 64>>>(enc, capl, out);
    conv_wdc<<<(VV * HH / 4 + 255) / 256, 256>>>(wdc_W);
    lt_kernel<<<BB, 256>>>(l_total);
    wq_kernel<<<(HH * HH * 4 + 255) / 256, 256>>>(W_hh);
    emb_gather<<<(TT * BB * EE + 255) / 256, 256>>>(emb_w);

    gemm_kernel<0><<<dim3(G4 / 128, 1), 256>>>(W_ih, b_ih, b_hh, nullptr);
    gemm_kernel<1><<<dim3(G4 / 128, (TT * BB + 127) / 128), 256>>>(W_ih, nullptr, nullptr, nullptr);

    for (int t = 0; t < TT; ++t)
        lstm_step<<<HH / 8, 512, 512 * 65 * 4>>>(t);

    conv_hid<<<(MPAD * HH / 4 + 255) / 256, 256>>>();
    zerofill<<<dim3(TT, BB), 256>>>(out);
    mma_vocab<<<dim3(VV / 128, MPAD / 128), 256, SMEM_VOC>>>(wdc_b, out);
}

// round 12
// speedup vs baseline: 1.2272x; 1.2272x over previous
#include <cuda_runtime.h>
#include <cuda_bf16.h>
#include <cstdint>
#include <math.h>

#define BB 64
#define TT 39
#define MAXLEN 40
#define FF 1024
#define EE 300
#define HH 512
#define G4 2048
#define VV 32000
#define XDIM 1324
#define MPAD 2560  // padded A rows for the MMA
#define S_SIMT 64  // n-tiles [0,64) -> fp32 SIMT path; [64,250) -> bf16 HMMA path

// ---------------- scratch (static device globals; no runtime alloc) ----------------
__device__ float g_lt[BB * FF];
__device__ int   g_si[BB];
__device__ int   g_dl[BB];
__device__ int   g_caps[BB * MAXLEN];
__device__ int   g_Mact;
__device__ int   g_act_src[TT * BB];
__device__ int   g_act_dst[TT * BB];
__device__ float g_base[BB * G4];
__device__ float g_Aemb[TT * BB * EE];
__device__ float g_gatepre[(size_t)TT * BB * G4];
__device__ float g_hall[(size_t)TT * BB * HH];
__device__ float g_c[BB * HH];
__device__ float g_Wq[HH * HH * 4];
// bf16 split operands for the tensor-core vocab GEMM
__device__ __nv_bfloat16 g_Bhi[(size_t)VV * HH];
__device__ __nv_bfloat16 g_Blo[(size_t)VV * HH];
__device__ __nv_bfloat16 g_Ahi[(size_t)MPAD * HH];
__device__ __nv_bfloat16 g_Alo[(size_t)MPAD * HH];

// ---------------- f32x2 helpers ----------------
#define FFMA2(acc, a, b) asm("fma.rn.f32x2 %0, %1, %2, %0;" : "+l"(acc) : "l"(a), "l"(b))
__device__ __forceinline__ unsigned long long PACK2(float x) {
    unsigned long long r;
    asm("mov.b64 %0, {%1, %1};" : "=l"(r) : "f"(x));
    return r;
}
__device__ __forceinline__ unsigned long long PACKF2(float lo, float hi) {
    unsigned long long r;
    asm("mov.b64 %0, {%1, %2};" : "=l"(r) : "f"(lo), "f"(hi));
    return r;
}
#define UNPACK2(lo, hi, v) asm("mov.b64 {%0, %1}, %2;" : "=f"(lo), "=f"(hi) : "l"(v))

// ---------------- baseline-PTX tensor helpers (valid on plain sm_103) ----------------
__device__ __forceinline__ uint32_t s2u(const void* p) {
    uint32_t a;
    asm("{ .reg .u64 t; cvta.to.shared.u64 t, %1; cvt.u32.u64 %0, t; }" : "=r"(a) : "l"(p));
    return a;
}

#define LDSM4(R, addr)                                                        \
    asm volatile("ldmatrix.sync.aligned.m8n8.x4.shared.b16 {%0,%1,%2,%3}, [%4];" \
                 : "=r"((R)[0]), "=r"((R)[1]), "=r"((R)[2]), "=r"((R)[3])     \
                 : "r"(addr))

#define MMA16816(C, A, B0, B1)                                                \
    asm volatile(                                                             \
        "mma.sync.aligned.m16n8k16.row.col.f32.bf16.bf16.f32 "                \
        "{%0,%1,%2,%3}, {%4,%5,%6,%7}, {%8,%9}, {%0,%1,%2,%3};"               \
        : "+f"((C)[0]), "+f"((C)[1]), "+f"((C)[2]), "+f"((C)[3])              \
        : "r"((A)[0]), "r"((A)[1]), "r"((A)[2]), "r"((A)[3]), "r"(B0), "r"(B1))

// ---------------- setup: sort, caps gather, compaction, aux outputs ----------------
__global__ void setup_kernel(const int* __restrict__ enc, const int* __restrict__ capl,
                             float* __restrict__ out) {
    __shared__ int len[BB];
    __shared__ int si[BB];
    int t = threadIdx.x;  // 64 threads
    if (t < BB) len[t] = capl[t];
    __syncthreads();
    if (t < BB) {
        int L = len[t];
        int r = 0;
        for (int j = 0; j < BB; ++j) {
            int Lj = len[j];
            if (Lj > L || (Lj == L && j < t)) r++;
        }
        si[r] = t;  // stable descending argsort
    }
    __syncthreads();
    const size_t OFF = (size_t)TT * BB * VV;
    if (t < BB) {
        int bsrc = si[t];
        g_si[t] = bsrc;
        int dl = len[bsrc] - 1;
        g_dl[t] = dl;
        for (int w = 0; w < MAXLEN; ++w) {
            int c = enc[bsrc * MAXLEN + w];
            g_caps[t * MAXLEN + w] = c;
            out[OFF + t * MAXLEN + w] = (float)c;
        }
        out[OFF + BB * MAXLEN + t] = (float)dl;
        out[OFF + BB * MAXLEN + BB + t] = (float)bsrc;
    }
    __syncthreads();
    if (t == 0) {
        int m = 0;
        for (int tt = 0; tt < TT; ++tt)
            for (int b = 0; b < BB; ++b)
                if (tt < g_dl[b]) {
                    g_act_src[m] = tt * BB + b;
                    g_act_dst[m] = b * TT + tt;
                    m++;
                }
        g_Mact = m;
        for (int i = m; i < TT * BB; ++i) { g_act_src[i] = 0; g_act_dst[i] = 0; }
    }
}

// lt_sorted[r] = sum_s l_total[s, sort_ind[r], :]
__global__ void lt_kernel(const float* __restrict__ l_total) {
    int r = blockIdx.x;
    int bsrc = g_si[r];
    for (int f = threadIdx.x; f < FF; f += blockDim.x) {
        float s = l_total[(size_t)0 * BB * FF + bsrc * FF + f]
                + l_total[(size_t)1 * BB * FF + bsrc * FF + f]
                + l_total[(size_t)2 * BB * FF + bsrc * FF + f];
        g_lt[r * FF + f] = s;
    }
}

// Wq[(j*512 + k)*4 + g] = W_hh[(g*512 + j)*512 + k]
__global__ void wq_kernel(const float* __restrict__ W_hh) {
    int idx = blockIdx.x * blockDim.x + threadIdx.x;
    if (idx < HH * HH * 4) {
        int g = idx & 3;
        int k = (idx >> 2) & (HH - 1);
        int j = idx >> 11;
        g_Wq[idx] = W_hh[(size_t)(g * HH + j) * HH + k];
    }
}

// gather embedding rows for all (t,b)
__global__ void emb_gather(const float* __restrict__ emb_w) {
    int idx = blockIdx.x * blockDim.x + threadIdx.x;
    const int total = TT * BB * EE;
    if (idx < total) {
        int m = idx / EE;
        int k = idx - m * EE;
        int tt = m >> 6;
        int b = m & 63;
        int tok = g_caps[b * MAXLEN + tt];
        g_Aemb[idx] = emb_w[(size_t)tok * EE + k];
    }
}

// ---------------- bf16 hi/lo split conversions ----------------
__device__ __forceinline__ void split4(float4 v, ushort4& hi, ushort4& lo) {
    __nv_bfloat16 h0 = __float2bfloat16(v.x);
    __nv_bfloat16 h1 = __float2bfloat16(v.y);
    __nv_bfloat16 h2 = __float2bfloat16(v.z);
    __nv_bfloat16 h3 = __float2bfloat16(v.w);
    __nv_bfloat16 l0 = __float2bfloat16(v.x - __bfloat162float(h0));
    __nv_bfloat16 l1 = __float2bfloat16(v.y - __bfloat162float(h1));
    __nv_bfloat16 l2 = __float2bfloat16(v.z - __bfloat162float(h2));
    __nv_bfloat16 l3 = __float2bfloat16(v.w - __bfloat162float(h3));
    hi.x = *(unsigned short*)&h0; hi.y = *(unsigned short*)&h1;
    hi.z = *(unsigned short*)&h2; hi.w = *(unsigned short*)&h3;
    lo.x = *(unsigned short*)&l0; lo.y = *(unsigned short*)&l1;
    lo.z = *(unsigned short*)&l2; lo.w = *(unsigned short*)&l3;
}

// only rows >= S_SIMT*128 are consumed by the HMMA branch
__global__ void conv_wdc(const float* __restrict__ W) {
    const int base4 = S_SIMT * 128 * (HH / 4);   // first converted float4 index
    int idx = blockIdx.x * blockDim.x + threadIdx.x;
    int i4 = base4 + idx;
    if (i4 < VV * HH / 4) {
        float4 v = ((const float4*)W)[i4];
        ushort4 hi, lo;
        split4(v, hi, lo);
        reinterpret_cast<ushort4*>(g_Bhi)[i4] = hi;
        reinterpret_cast<ushort4*>(g_Blo)[i4] = lo;
    }
}

__global__ void conv_hid() {
    int i4 = blockIdx.x * blockDim.x + threadIdx.x;
    if (i4 < MPAD * HH / 4) {
        int m = i4 >> 7;
        int k4 = i4 & 127;
        int Mact = g_Mact;
        int src = g_act_src[m < Mact ? m : (Mact - 1)];
        float4 v = *(const float4*)(g_hall + (size_t)src * HH + (k4 << 2));
        ushort4 hi, lo;
        split4(v, hi, lo);
        reinterpret_cast<ushort4*>(g_Ahi)[i4] = hi;
        reinterpret_cast<ushort4*>(g_Alo)[i4] = lo;
    }
}

// ---------------- SIMT SGEMM for the small pre-GEMMs (modes 0/1) ----------------
template <int MODE>
__global__ void __launch_bounds__(256, 2)
gemm_kernel(const float* __restrict__ Bm, const float* __restrict__ bias1,
            const float* __restrict__ bias2, float* __restrict__ Cout) {
    constexpr int K   = (MODE == 0) ? 1024 : 300;
    constexpr int LDA = (MODE == 0) ? 1024 : 300;
    constexpr int LDB = XDIM;
    constexpr int BC0 = (MODE == 0) ? 300 : 0;

    const float* A = (MODE == 0) ? g_lt : g_Aemb;
    int M_eff = (MODE == 0) ? 64 : (TT * BB);

    int m0 = blockIdx.y * 128;
    int n0 = blockIdx.x * 128;
    if (m0 >= M_eff) return;

    __shared__ float As[8][128];
    __shared__ float Bs[8][128];

    int tid = threadIdx.x;
    int lrow = tid & 127;
    int kq = (tid >> 7) << 2;
    int tx = tid & 15;
    int ty = tid >> 4;

    int am = min(m0 + lrow, M_eff - 1);
    const float* Ap = A + (size_t)am * LDA;
    const float* Bp = Bm + (size_t)(n0 + lrow) * LDB + BC0;

    unsigned long long acc[8][4];
#pragma unroll
    for (int i = 0; i < 8; ++i)
#pragma unroll
        for (int p = 0; p < 4; ++p) acc[i][p] = 0ull;

    const int nkt = (K + 7) >> 3;
    for (int kt = 0; kt < nkt; ++kt) {
        int kk = (kt << 3) + kq;
        float4 av, bv;
        if (kk + 3 < K) {
            av = *(const float4*)(Ap + kk);
            bv = *(const float4*)(Bp + kk);
        } else {
            av.x = (kk + 0 < K) ? Ap[kk + 0] : 0.f;
            av.y = (kk + 1 < K) ? Ap[kk + 1] : 0.f;
            av.z = (kk + 2 < K) ? Ap[kk + 2] : 0.f;
            av.w = (kk + 3 < K) ? Ap[kk + 3] : 0.f;
            bv.x = (kk + 0 < K) ? Bp[kk + 0] : 0.f;
            bv.y = (kk + 1 < K) ? Bp[kk + 1] : 0.f;
            bv.z = (kk + 2 < K) ? Bp[kk + 2] : 0.f;
            bv.w = (kk + 3 < K) ? Bp[kk + 3] : 0.f;
        }
        __syncthreads();
        As[kq + 0][lrow] = av.x; As[kq + 1][lrow] = av.y;
        As[kq + 2][lrow] = av.z; As[kq + 3][lrow] = av.w;
        Bs[kq + 0][lrow] = bv.x; Bs[kq + 1][lrow] = bv.y;
        Bs[kq + 2][lrow] = bv.z; Bs[kq + 3][lrow] = bv.w;
        __syncthreads();
#pragma unroll
        for (int k = 0; k < 8; ++k) {
            float4 a0 = *(const float4*)&As[k][ty * 8];
            float4 a1 = *(const float4*)&As[k][ty * 8 + 4];
            ulonglong2 b0 = *(const ulonglong2*)&Bs[k][tx * 8];
            ulonglong2 b1 = *(const ulonglong2*)&Bs[k][tx * 8 + 4];
            float amv[8] = {a0.x, a0.y, a0.z, a0.w, a1.x, a1.y, a1.z, a1.w};
#pragma unroll
            for (int i = 0; i < 8; ++i) {
                unsigned long long ap = PACK2(amv[i]);
                FFMA2(acc[i][0], ap, b0.x);
                FFMA2(acc[i][1], ap, b0.y);
                FFMA2(acc[i][2], ap, b1.x);
                FFMA2(acc[i][3], ap, b1.y);
            }
        }
    }

#pragma unroll
    for (int i = 0; i < 8; ++i) {
        int m = m0 + ty * 8 + i;
        if (m >= M_eff) continue;
#pragma unroll
        for (int p = 0; p < 4; ++p) {
            float lo, hi;
            UNPACK2(lo, hi, acc[i][p]);
            int n = n0 + tx * 8 + p * 2;
            if (MODE == 0) {
                g_base[(size_t)m * G4 + n + 0] = lo + bias1[n + 0] + bias2[n + 0];
                g_base[(size_t)m * G4 + n + 1] = hi + bias1[n + 1] + bias2[n + 1];
            } else {
                int b = m & 63;
                g_gatepre[(size_t)m * G4 + n + 0] = lo + g_base[(size_t)b * G4 + n + 0];
                g_gatepre[(size_t)m * G4 + n + 1] = hi + g_base[(size_t)b * G4 + n + 1];
            }
        }
    }
}

// ---------------- LSTM recurrence step ----------------
__global__ void lstm_step(int t) {
    extern __shared__ float hs[];  // [512][65] padded
    int tid = threadIdx.x;         // 512
    int b = tid & 63;
    int jj = tid >> 6;
    int j = blockIdx.x * 8 + jj;

    if (t > 0) {
        const float* hp = g_hall + (size_t)(t - 1) * BB * HH;
        for (int i = tid; i < BB * HH; i += 512) {
            int bb = i >> 9;
            int k = i & 511;
            hs[k * 65 + bb] = hp[i];
        }
        __syncthreads();
    }

    const float* gp = g_gatepre + ((size_t)t * BB + b) * G4 + j;
    float a0 = gp[0], a1 = gp[HH], a2 = gp[2 * HH], a3 = gp[3 * HH];

    if (t > 0) {
        unsigned long long accA = PACKF2(a0, a1);
        unsigned long long accB = PACKF2(a2, a3);
        const ulonglong2* W2 = (const ulonglong2*)(g_Wq + (size_t)j * HH * 4);
#pragma unroll 8
        for (int k = 0; k < HH; ++k) {
            unsigned long long hp2 = PACK2(hs[k * 65 + b]);
            ulonglong2 w = W2[k];
            FFMA2(accA, hp2, w.x);
            FFMA2(accB, hp2, w.y);
        }
        UNPACK2(a0, a1, accA);
        UNPACK2(a2, a3, accB);
    }

    float iv = 1.f / (1.f + expf(-a0));
    float fv = 1.f / (1.f + expf(-a1));
    float gv = tanhf(a2);
    float ov = 1.f / (1.f + expf(-a3));
    float cprev = (t > 0) ? g_c[b * HH + j] : 0.f;
    float c = fv * cprev + iv * gv;
    g_c[b * HH + j] = c;
    float h = ov * tanhf(c);
    g_hall[((size_t)t * BB + b) * HH + j] = h;
}

// zero masked prediction rows
__global__ void zerofill(float* __restrict__ out) {
    int tt = blockIdx.x;
    int b = blockIdx.y;
    if (tt < g_dl[b]) return;
    float4* p = (float4*)(out + ((size_t)b * TT + tt) * VV);
    float4 z = make_float4(0.f, 0.f, 0.f, 0.f);
    for (int i = threadIdx.x; i < VV / 4; i += blockDim.x) p[i] = z;
}

// ---------------- hybrid vocab GEMM: SIMT fp32 tiles + bf16-HMMA tiles ----------------
// n-tiles [0, S_SIMT): fp32 f32x2 SIMT path (FMA pipe), exact R3 math.
// n-tiles [S_SIMT, 250): bf16 3-term HMMA path (tensor pipe), exact R7 math.
// Co-resident CTAs of the two flavors overlap on different pipes.
#define VSTRIDE 80
#define OP_BYTES (128 * VSTRIDE)   // 10240
#define SMEM_VOC (4 * OP_BYTES)    // 40960 (HMMA uses 4 operands; SIMT uses first 8KB)

__global__ void __launch_bounds__(256, 2)
mma_vocab(const float* __restrict__ bias, const float* __restrict__ wdc,
          float* __restrict__ out) {
    int Mact = g_Mact;
    int m0 = blockIdx.y << 7;
    if (m0 >= Mact) return;
    int n0 = blockIdx.x << 7;

    extern __shared__ char smem[];
    int tid = threadIdx.x;

    if (blockIdx.x < S_SIMT) {
        // ---------- fp32 SIMT tile (FMA pipe) ----------
        float* As = (float*)smem;        // [8][128]
        float* Bs = As + 8 * 128;        // [8][128]
        int lrow = tid & 127;
        int kq = (tid >> 7) << 2;
        int tx = tid & 15;
        int ty = tid >> 4;

        int am = min(m0 + lrow, Mact - 1);
        const float* Ap = g_hall + (size_t)g_act_src[am] * HH;
        const float* Bp = wdc + (size_t)(n0 + lrow) * HH;

        unsigned long long acc[8][4];
#pragma unroll
        for (int i = 0; i < 8; ++i)
#pragma unroll
            for (int p = 0; p < 4; ++p) acc[i][p] = 0ull;

#pragma unroll 1
        for (int kt = 0; kt < HH / 8; ++kt) {
            int kk = (kt << 3) + kq;
            float4 av = *(const float4*)(Ap + kk);
            float4 bv = *(const float4*)(Bp + kk);
            __syncthreads();
            As[(kq + 0) * 128 + lrow] = av.x; As[(kq + 1) * 128 + lrow] = av.y;
            As[(kq + 2) * 128 + lrow] = av.z; As[(kq + 3) * 128 + lrow] = av.w;
            Bs[(kq + 0) * 128 + lrow] = bv.x; Bs[(kq + 1) * 128 + lrow] = bv.y;
            Bs[(kq + 2) * 128 + lrow] = bv.z; Bs[(kq + 3) * 128 + lrow] = bv.w;
            __syncthreads();
#pragma unroll
            for (int k = 0; k < 8; ++k) {
                float4 a0 = *(const float4*)&As[k * 128 + ty * 8];
                float4 a1 = *(const float4*)&As[k * 128 + ty * 8 + 4];
                ulonglong2 b0 = *(const ulonglong2*)&Bs[k * 128 + tx * 8];
                ulonglong2 b1 = *(const ulonglong2*)&Bs[k * 128 + tx * 8 + 4];
                float amv[8] = {a0.x, a0.y, a0.z, a0.w, a1.x, a1.y, a1.z, a1.w};
#pragma unroll
                for (int i = 0; i < 8; ++i) {
                    unsigned long long ap = PACK2(amv[i]);
                    FFMA2(acc[i][0], ap, b0.x);
                    FFMA2(acc[i][1], ap, b0.y);
                    FFMA2(acc[i][2], ap, b1.x);
                    FFMA2(acc[i][3], ap, b1.y);
                }
            }
        }

#pragma unroll
        for (int i = 0; i < 8; ++i) {
            int m = m0 + ty * 8 + i;
            if (m >= Mact) continue;
            size_t dst = (size_t)g_act_dst[m] * VV;
#pragma unroll
            for (int p = 0; p < 4; ++p) {
                float lo, hi;
                UNPACK2(lo, hi, acc[i][p]);
                int n = n0 + tx * 8 + p * 2;
                out[dst + n + 0] = lo + bias[n + 0];
                out[dst + n + 1] = hi + bias[n + 1];
            }
        }
        return;
    }

    // ---------- bf16 3-term HMMA tile (tensor pipe) ----------
    const uint32_t sb = s2u(smem);
    const uint32_t sAh = sb;
    const uint32_t sAl = sb + OP_BYTES;
    const uint32_t sBh = sb + 2 * OP_BYTES;
    const uint32_t sBl = sb + 3 * OP_BYTES;

    int warp = tid >> 5;
    int lane = tid & 31;
    int wm = warp >> 1;  // 0..3
    int wn = warp & 1;   // 0..1

    float c[2][8][4];
#pragma unroll
    for (int mf = 0; mf < 2; ++mf)
#pragma unroll
        for (int nf = 0; nf < 8; ++nf)
#pragma unroll
            for (int q = 0; q < 4; ++q) c[mf][nf][q] = 0.f;

    // per-thread load slots: 2 x 16B units per operand per chunk
    int u0 = tid * 2;
    int lr0 = u0 >> 2, lc0 = u0 & 3;
    int lr1 = (u0 + 1) >> 2, lc1 = (u0 + 1) & 3;
    uint32_t so0 = (uint32_t)(lr0 * VSTRIDE + lc0 * 16);
    uint32_t so1 = (uint32_t)(lr1 * VSTRIDE + lc1 * 16);

    uint32_t a_off[2], b_off[4];
#pragma unroll
    for (int mf = 0; mf < 2; ++mf)
        a_off[mf] = (uint32_t)((wm * 32 + mf * 16 + (lane & 15)) * VSTRIDE + ((lane >> 4) << 4));
#pragma unroll
    for (int g = 0; g < 4; ++g)
        b_off[g] = (uint32_t)((wn * 64 + g * 16 + (lane & 15)) * VSTRIDE + ((lane >> 4) << 4));

#pragma unroll 1
    for (int ch = 0; ch < 16; ++ch) {
        int col0 = ch * 32;
        __syncthreads();
        {
            const __nv_bfloat16* pAh = g_Ahi + (size_t)m0 * HH + col0;
            const __nv_bfloat16* pAl = g_Alo + (size_t)m0 * HH + col0;
            const __nv_bfloat16* pBh = g_Bhi + (size_t)n0 * HH + col0;
            const __nv_bfloat16* pBl = g_Blo + (size_t)n0 * HH + col0;
            uint4 vah0 = *(const uint4*)(pAh + (size_t)lr0 * HH + lc0 * 8);
            uint4 vah1 = *(const uint4*)(pAh + (size_t)lr1 * HH + lc1 * 8);
            uint4 val0 = *(const uint4*)(pAl + (size_t)lr0 * HH + lc0 * 8);
            uint4 val1 = *(const uint4*)(pAl + (size_t)lr1 * HH + lc1 * 8);
            uint4 vbh0 = *(const uint4*)(pBh + (size_t)lr0 * HH + lc0 * 8);
            uint4 vbh1 = *(const uint4*)(pBh + (size_t)lr1 * HH + lc1 * 8);
            uint4 vbl0 = *(const uint4*)(pBl + (size_t)lr0 * HH + lc0 * 8);
            uint4 vbl1 = *(const uint4*)(pBl + (size_t)lr1 * HH + lc1 * 8);
            *(uint4*)(smem + (sAh - sb) + so0) = vah0;
            *(uint4*)(smem + (sAh - sb) + so1) = vah1;
            *(uint4*)(smem + (sAl - sb) + so0) = val0;
            *(uint4*)(smem + (sAl - sb) + so1) = val1;
            *(uint4*)(smem + (sBh - sb) + so0) = vbh0;
            *(uint4*)(smem + (sBh - sb) + so1) = vbh1;
            *(uint4*)(smem + (sBl - sb) + so0) = vbl0;
            *(uint4*)(smem + (sBl - sb) + so1) = vbl1;
        }
        __syncthreads();

#pragma unroll
        for (int ks = 0; ks < 2; ++ks) {
            uint32_t koff = (uint32_t)(ks * 32);
            uint32_t ah[2][4], al[2][4];
#pragma unroll
            for (int mf = 0; mf < 2; ++mf) {
                LDSM4(ah[mf], sAh + a_off[mf] + koff);
                LDSM4(al[mf], sAl + a_off[mf] + koff);
            }
#pragma unroll
            for (int g = 0; g < 4; ++g) {
                uint32_t bh[4], bl[4];
                LDSM4(bh, sBh + b_off[g] + koff);
                LDSM4(bl, sBl + b_off[g] + koff);
                // x4 frag order: r0 = n0-7/k0-7, r1 = n8-15/k0-7, r2 = n0-7/k8-15, r3 = n8-15/k8-15
#pragma unroll
                for (int mf = 0; mf < 2; ++mf) {
                    MMA16816(c[mf][2 * g + 0], ah[mf], bh[0], bh[2]);  // Ah*Bh
                    MMA16816(c[mf][2 * g + 0], al[mf], bh[0], bh[2]);  // Al*Bh
                    MMA16816(c[mf][2 * g + 0], ah[mf], bl[0], bl[2]);  // Ah*Bl
                    MMA16816(c[mf][2 * g + 1], ah[mf], bh[1], bh[3]);
                    MMA16816(c[mf][2 * g + 1], al[mf], bh[1], bh[3]);
                    MMA16816(c[mf][2 * g + 1], ah[mf], bl[1], bl[3]);
                }
            }
        }
    }

    // epilogue: frag (mf,nf): c0,c1 -> row tq, cols 2*tr+{0,1}; c2,c3 -> row tq+8
    int tq = lane >> 2;
    int tr = lane & 3;
#pragma unroll
    for (int mf = 0; mf < 2; ++mf) {
#pragma unroll
        for (int half = 0; half < 2; ++half) {
            int m = m0 + wm * 32 + mf * 16 + half * 8 + tq;
            if (m >= Mact) continue;
            size_t dst = (size_t)g_act_dst[m] * VV;
#pragma unroll
            for (int nf = 0; nf < 8; ++nf) {
                int n = n0 + wn * 64 + nf * 8 + tr * 2;
                float2 v;
                v.x = c[mf][nf][half * 2 + 0] + bias[n + 0];
                v.y = c[mf][nf][half * 2 + 1] + bias[n + 1];
                *(float2*)(out + dst + n) = v;
            }
        }
    }
}

// ---------------- launch ----------------
extern "C" void kernel_launch(void* const* d_in, const int* in_sizes, int n_in,
                              void* d_out, int out_size) {
    const float* l_total = (const float*)d_in[0];
    const int*   enc     = (const int*)d_in[1];
    const int*   capl    = (const int*)d_in[2];
    const float* emb_w   = (const float*)d_in[3];
    const float* W_ih    = (const float*)d_in[4];
    const float* W_hh    = (const float*)d_in[5];
    const float* b_ih    = (const float*)d_in[6];
    const float* b_hh    = (const float*)d_in[7];
    const float* wdc_W   = (const float*)d_in[8];
    const float* wdc_b   = (const float*)d_in[9];
    float* out = (float*)d_out;

    cudaFuncSetAttribute(lstm_step, cudaFuncAttributeMaxDynamicSharedMemorySize, 512 * 65 * 4);
    cudaFuncSetAttribute(mma_vocab, cudaFuncAttributeMaxDynamicSharedMemorySize, SMEM_VOC);

    setup_kernel<<<1, 64>>>(enc, capl, out);
    {
        const int n4 = (VV - S_SIMT * 128) * (HH / 4);
        conv_wdc<<<(n4 + 255) / 256, 256>>>(wdc_W);
    }
    lt_kernel<<<BB, 256>>>(l_total);
    wq_kernel<<<(HH * HH * 4 + 255) / 256, 256>>>(W_hh);
    emb_gather<<<(TT * BB * EE + 255) / 256, 256>>>(emb_w);

    gemm_kernel<0><<<dim3(G4 / 128, 1), 256>>>(W_ih, b_ih, b_hh, nullptr);
    gemm_kernel<1><<<dim3(G4 / 128, (TT * BB + 127) / 128), 256>>>(W_ih, nullptr, nullptr, nullptr);

    for (int t = 0; t < TT; ++t)
        lstm_step<<<HH / 8, 512, 512 * 65 * 4>>>(t);

    conv_hid<<<(MPAD * HH / 4 + 255) / 256, 256>>>();
    zerofill<<<dim3(TT, BB), 256>>>(out);
    mma_vocab<<<dim3(VV / 128, MPAD / 128), 256, SMEM_VOC>>>(wdc_b, wdc_W, out);
}

// round 16
// speedup vs baseline: 1.9596x; 1.5968x over previous
#include <cuda_runtime.h>
#include <cuda_bf16.h>
#include <cstdint>
#include <math.h>

#define BB 64
#define TT 39
#define MAXLEN 40
#define FF 1024
#define EE 300
#define HH 512
#define G4 2048
#define VV 32000
#define XDIM 1324
#define MPAD 2560  // padded A rows for the MMA

// ---------------- scratch (static device globals; no runtime alloc) ----------------
__device__ float g_lt[BB * FF];
__device__ int   g_si[BB];
__device__ int   g_dl[BB];
__device__ int   g_caps[BB * MAXLEN];
__device__ int   g_Mact;
__device__ int   g_bar;           // persistent-LSTM global barrier counter
__device__ int   g_act_src[TT * BB];
__device__ int   g_act_dst[TT * BB];
__device__ float g_base[BB * G4];
__device__ float g_Aemb[TT * BB * EE];
__device__ float g_gatepre[(size_t)TT * BB * G4];
__device__ float g_hall[(size_t)TT * BB * HH];
__device__ float g_Wq[HH * HH * 4];
// bf16 split operands for the tensor-core vocab GEMM
__device__ __nv_bfloat16 g_Bhi[(size_t)VV * HH];
__device__ __nv_bfloat16 g_Blo[(size_t)VV * HH];
__device__ __nv_bfloat16 g_Ahi[(size_t)MPAD * HH];
__device__ __nv_bfloat16 g_Alo[(size_t)MPAD * HH];

// ---------------- f32x2 helpers ----------------
#define FFMA2(acc, a, b) asm("fma.rn.f32x2 %0, %1, %2, %0;" : "+l"(acc) : "l"(a), "l"(b))
__device__ __forceinline__ unsigned long long PACK2(float x) {
    unsigned long long r;
    asm("mov.b64 %0, {%1, %1};" : "=l"(r) : "f"(x));
    return r;
}
__device__ __forceinline__ unsigned long long PACKF2(float lo, float hi) {
    unsigned long long r;
    asm("mov.b64 %0, {%1, %2};" : "=l"(r) : "f"(lo), "f"(hi));
    return r;
}
#define UNPACK2(lo, hi, v) asm("mov.b64 {%0, %1}, %2;" : "=f"(lo), "=f"(hi) : "l"(v))

// ---------------- baseline-PTX tensor helpers (valid on plain sm_103) ----------------
__device__ __forceinline__ uint32_t s2u(const void* p) {
    uint32_t a;
    asm("{ .reg .u64 t; cvta.to.shared.u64 t, %1; cvt.u32.u64 %0, t; }" : "=r"(a) : "l"(p));
    return a;
}

#define LDSM4(R, addr)                                                        \
    asm volatile("ldmatrix.sync.aligned.m8n8.x4.shared.b16 {%0,%1,%2,%3}, [%4];" \
                 : "=r"((R)[0]), "=r"((R)[1]), "=r"((R)[2]), "=r"((R)[3])     \
                 : "r"(addr))

#define MMA16816(C, A, B0, B1)                                                \
    asm volatile(                                                             \
        "mma.sync.aligned.m16n8k16.row.col.f32.bf16.bf16.f32 "                \
        "{%0,%1,%2,%3}, {%4,%5,%6,%7}, {%8,%9}, {%0,%1,%2,%3};"               \
        : "+f"((C)[0]), "+f"((C)[1]), "+f"((C)[2]), "+f"((C)[3])              \
        : "r"((A)[0]), "r"((A)[1]), "r"((A)[2]), "r"((A)[3]), "r"(B0), "r"(B1))

// ---------------- setup: sort, caps gather, compaction, aux outputs ----------------
__global__ void setup_kernel(const int* __restrict__ enc, const int* __restrict__ capl,
                             float* __restrict__ out) {
    __shared__ int len[BB];
    __shared__ int si[BB];
    int t = threadIdx.x;  // 64 threads
    if (t < BB) len[t] = capl[t];
    __syncthreads();
    if (t < BB) {
        int L = len[t];
        int r = 0;
        for (int j = 0; j < BB; ++j) {
            int Lj = len[j];
            if (Lj > L || (Lj == L && j < t)) r++;
        }
        si[r] = t;  // stable descending argsort
    }
    __syncthreads();
    const size_t OFF = (size_t)TT * BB * VV;
    if (t < BB) {
        int bsrc = si[t];
        g_si[t] = bsrc;
        int dl = len[bsrc] - 1;
        g_dl[t] = dl;
        for (int w = 0; w < MAXLEN; ++w) {
            int c = enc[bsrc * MAXLEN + w];
            g_caps[t * MAXLEN + w] = c;
            out[OFF + t * MAXLEN + w] = (float)c;
        }
        out[OFF + BB * MAXLEN + t] = (float)dl;
        out[OFF + BB * MAXLEN + BB + t] = (float)bsrc;
    }
    __syncthreads();
    if (t == 0) {
        g_bar = 0;  // reset persistent-LSTM barrier every launch (graph replays!)
        int m = 0;
        for (int tt = 0; tt < TT; ++tt)
            for (int b = 0; b < BB; ++b)
                if (tt < g_dl[b]) {
                    g_act_src[m] = tt * BB + b;
                    g_act_dst[m] = b * TT + tt;
                    m++;
                }
        g_Mact = m;
        for (int i = m; i < TT * BB; ++i) { g_act_src[i] = 0; g_act_dst[i] = 0; }
    }
}

// lt_sorted[r] = sum_s l_total[s, sort_ind[r], :]
__global__ void lt_kernel(const float* __restrict__ l_total) {
    int r = blockIdx.x;
    int bsrc = g_si[r];
    for (int f = threadIdx.x; f < FF; f += blockDim.x) {
        float s = l_total[(size_t)0 * BB * FF + bsrc * FF + f]
                + l_total[(size_t)1 * BB * FF + bsrc * FF + f]
                + l_total[(size_t)2 * BB * FF + bsrc * FF + f];
        g_lt[r * FF + f] = s;
    }
}

// Wq[(j*512 + k)*4 + g] = W_hh[(g*512 + j)*512 + k]
__global__ void wq_kernel(const float* __restrict__ W_hh) {
    int idx = blockIdx.x * blockDim.x + threadIdx.x;
    if (idx < HH * HH * 4) {
        int g = idx & 3;
        int k = (idx >> 2) & (HH - 1);
        int j = idx >> 11;
        g_Wq[idx] = W_hh[(size_t)(g * HH + j) * HH + k];
    }
}

// gather embedding rows for all (t,b)
__global__ void emb_gather(const float* __restrict__ emb_w) {
    int idx = blockIdx.x * blockDim.x + threadIdx.x;
    const int total = TT * BB * EE;
    if (idx < total) {
        int m = idx / EE;
        int k = idx - m * EE;
        int tt = m >> 6;
        int b = m & 63;
        int tok = g_caps[b * MAXLEN + tt];
        g_Aemb[idx] = emb_w[(size_t)tok * EE + k];
    }
}

// ---------------- bf16 hi/lo split conversions ----------------
__device__ __forceinline__ void split4(float4 v, ushort4& hi, ushort4& lo) {
    __nv_bfloat16 h0 = __float2bfloat16(v.x);
    __nv_bfloat16 h1 = __float2bfloat16(v.y);
    __nv_bfloat16 h2 = __float2bfloat16(v.z);
    __nv_bfloat16 h3 = __float2bfloat16(v.w);
    __nv_bfloat16 l0 = __float2bfloat16(v.x - __bfloat162float(h0));
    __nv_bfloat16 l1 = __float2bfloat16(v.y - __bfloat162float(h1));
    __nv_bfloat16 l2 = __float2bfloat16(v.z - __bfloat162float(h2));
    __nv_bfloat16 l3 = __float2bfloat16(v.w - __bfloat162float(h3));
    hi.x = *(unsigned short*)&h0; hi.y = *(unsigned short*)&h1;
    hi.z = *(unsigned short*)&h2; hi.w = *(unsigned short*)&h3;
    lo.x = *(unsigned short*)&l0; lo.y = *(unsigned short*)&l1;
    lo.z = *(unsigned short*)&l2; lo.w = *(unsigned short*)&l3;
}

__global__ void conv_wdc(const float* __restrict__ W) {
    int i4 = blockIdx.x * blockDim.x + threadIdx.x;
    if (i4 < VV * HH / 4) {
        float4 v = ((const float4*)W)[i4];
        ushort4 hi, lo;
        split4(v, hi, lo);
        reinterpret_cast<ushort4*>(g_Bhi)[i4] = hi;
        reinterpret_cast<ushort4*>(g_Blo)[i4] = lo;
    }
}

__global__ void conv_hid() {
    int i4 = blockIdx.x * blockDim.x + threadIdx.x;
    if (i4 < MPAD * HH / 4) {
        int m = i4 >> 7;
        int k4 = i4 & 127;
        int Mact = g_Mact;
        int src = g_act_src[m < Mact ? m : (Mact - 1)];
        float4 v = *(const float4*)(g_hall + (size_t)src * HH + (k4 << 2));
        ushort4 hi, lo;
        split4(v, hi, lo);
        reinterpret_cast<ushort4*>(g_Ahi)[i4] = hi;
        reinterpret_cast<ushort4*>(g_Alo)[i4] = lo;
    }
}

// ---------------- SIMT SGEMM for the small pre-GEMMs (modes 0/1) ----------------
template <int MODE>
__global__ void __launch_bounds__(256, 2)
gemm_kernel(const float* __restrict__ Bm, const float* __restrict__ bias1,
            const float* __restrict__ bias2, float* __restrict__ Cout) {
    constexpr int K   = (MODE == 0) ? 1024 : 300;
    constexpr int LDA = (MODE == 0) ? 1024 : 300;
    constexpr int LDB = XDIM;
    constexpr int BC0 = (MODE == 0) ? 300 : 0;

    const float* A = (MODE == 0) ? g_lt : g_Aemb;
    int M_eff = (MODE == 0) ? 64 : (TT * BB);

    int m0 = blockIdx.y * 128;
    int n0 = blockIdx.x * 128;
    if (m0 >= M_eff) return;

    __shared__ float As[8][128];
    __shared__ float Bs[8][128];

    int tid = threadIdx.x;
    int lrow = tid & 127;
    int kq = (tid >> 7) << 2;
    int tx = tid & 15;
    int ty = tid >> 4;

    int am = min(m0 + lrow, M_eff - 1);
    const float* Ap = A + (size_t)am * LDA;
    const float* Bp = Bm + (size_t)(n0 + lrow) * LDB + BC0;

    unsigned long long acc[8][4];
#pragma unroll
    for (int i = 0; i < 8; ++i)
#pragma unroll
        for (int p = 0; p < 4; ++p) acc[i][p] = 0ull;

    const int nkt = (K + 7) >> 3;
    for (int kt = 0; kt < nkt; ++kt) {
        int kk = (kt << 3) + kq;
        float4 av, bv;
        if (kk + 3 < K) {
            av = *(const float4*)(Ap + kk);
            bv = *(const float4*)(Bp + kk);
        } else {
            av.x = (kk + 0 < K) ? Ap[kk + 0] : 0.f;
            av.y = (kk + 1 < K) ? Ap[kk + 1] : 0.f;
            av.z = (kk + 2 < K) ? Ap[kk + 2] : 0.f;
            av.w = (kk + 3 < K) ? Ap[kk + 3] : 0.f;
            bv.x = (kk + 0 < K) ? Bp[kk + 0] : 0.f;
            bv.y = (kk + 1 < K) ? Bp[kk + 1] : 0.f;
            bv.z = (kk + 2 < K) ? Bp[kk + 2] : 0.f;
            bv.w = (kk + 3 < K) ? Bp[kk + 3] : 0.f;
        }
        __syncthreads();
        As[kq + 0][lrow] = av.x; As[kq + 1][lrow] = av.y;
        As[kq + 2][lrow] = av.z; As[kq + 3][lrow] = av.w;
        Bs[kq + 0][lrow] = bv.x; Bs[kq + 1][lrow] = bv.y;
        Bs[kq + 2][lrow] = bv.z; Bs[kq + 3][lrow] = bv.w;
        __syncthreads();
#pragma unroll
        for (int k = 0; k < 8; ++k) {
            float4 a0 = *(const float4*)&As[k][ty * 8];
            float4 a1 = *(const float4*)&As[k][ty * 8 + 4];
            ulonglong2 b0 = *(const ulonglong2*)&Bs[k][tx * 8];
            ulonglong2 b1 = *(const ulonglong2*)&Bs[k][tx * 8 + 4];
            float amv[8] = {a0.x, a0.y, a0.z, a0.w, a1.x, a1.y, a1.z, a1.w};
#pragma unroll
            for (int i = 0; i < 8; ++i) {
                unsigned long long ap = PACK2(amv[i]);
                FFMA2(acc[i][0], ap, b0.x);
                FFMA2(acc[i][1], ap, b0.y);
                FFMA2(acc[i][2], ap, b1.x);
                FFMA2(acc[i][3], ap, b1.y);
            }
        }
    }

#pragma unroll
    for (int i = 0; i < 8; ++i) {
        int m = m0 + ty * 8 + i;
        if (m >= M_eff) continue;
#pragma unroll
        for (int p = 0; p < 4; ++p) {
            float lo, hi;
            UNPACK2(lo, hi, acc[i][p]);
            int n = n0 + tx * 8 + p * 2;
            if (MODE == 0) {
                g_base[(size_t)m * G4 + n + 0] = lo + bias1[n + 0] + bias2[n + 0];
                g_base[(size_t)m * G4 + n + 1] = hi + bias1[n + 1] + bias2[n + 1];
            } else {
                int b = m & 63;
                g_gatepre[(size_t)m * G4 + n + 0] = lo + g_base[(size_t)b * G4 + n + 0];
                g_gatepre[(size_t)m * G4 + n + 1] = hi + g_base[(size_t)b * G4 + n + 1];
            }
        }
    }
}

// ---------------- persistent fused LSTM: all 39 steps in ONE kernel ----------------
// 64 CTAs x 512 threads, 1 CTA/SM (big smem) -> all co-resident, spin barrier safe.
// CTA c owns j in [c*8, c*8+8). W_hh slice staged to smem ONCE; c-state in regs.
#define LSTM_SMEM (8 * 2048 * 4 + 512 * 65 * 4)  // 65536 + 133120 = 198656 B

__global__ void __launch_bounds__(512, 1) lstm_persist() {
    extern __shared__ float sm[];
    float* Ws = sm;                 // [8 jj][512 k][4 gates]
    float* hs = sm + 8 * 2048;      // [512 k][65 b-padded]
    int tid = threadIdx.x;
    int b = tid & 63;
    int jj = tid >> 6;
    int j = blockIdx.x * 8 + jj;

    // stage this CTA's W_hh slice once
    {
        const float4* wsrc = (const float4*)(g_Wq + (size_t)blockIdx.x * 8 * 2048);
        float4* wdst = (float4*)Ws;
        for (int i = tid; i < 8 * 2048 / 4; i += 512) wdst[i] = wsrc[i];
    }
    __syncthreads();

    const ulonglong2* W2 = (const ulonglong2*)(Ws + (size_t)jj * 2048);
    float c = 0.f;

#pragma unroll 1
    for (int t = 0; t < TT; ++t) {
        float a0, a1, a2, a3;
        {
            const float* gp = g_gatepre + ((size_t)t * BB + b) * G4 + j;
            a0 = gp[0]; a1 = gp[HH]; a2 = gp[2 * HH]; a3 = gp[3 * HH];
        }

        if (t > 0) {
            // global barrier: wait until all 64 CTAs committed h(t-1)
            if (tid == 0) {
                int tgt = 64 * t;
                while (*((volatile int*)&g_bar) < tgt) __nanosleep(32);
            }
            __syncthreads();
            // reload h(t-1) (L2-fresh region; __ldcg bypasses L1)
            const float* hp = g_hall + (size_t)(t - 1) * BB * HH;
            for (int i = tid; i < BB * HH; i += 512)
                hs[(i & 511) * 65 + (i >> 9)] = __ldcg(hp + i);
            __syncthreads();

            unsigned long long accA = PACKF2(a0, a1);
            unsigned long long accB = PACKF2(a2, a3);
#pragma unroll 8
            for (int k = 0; k < HH; ++k) {
                unsigned long long hp2 = PACK2(hs[k * 65 + b]);
                ulonglong2 w = W2[k];
                FFMA2(accA, hp2, w.x);
                FFMA2(accB, hp2, w.y);
            }
            UNPACK2(a0, a1, accA);
            UNPACK2(a2, a3, accB);
        }

        float iv = 1.f / (1.f + expf(-a0));
        float fv = 1.f / (1.f + expf(-a1));
        float gv = tanhf(a2);
        float ov = 1.f / (1.f + expf(-a3));
        c = fv * c + iv * gv;
        float h = ov * tanhf(c);
        g_hall[((size_t)t * BB + b) * HH + j] = h;

        __syncthreads();  // all stores of this CTA issued; hs safe to overwrite next iter
        if (tid == 0) {
            __threadfence();        // release h(t) to L2
            atomicAdd(&g_bar, 1);
        }
    }
}

// zero masked prediction rows
__global__ void zerofill(float* __restrict__ out) {
    int tt = blockIdx.x;
    int b = blockIdx.y;
    if (tt < g_dl[b]) return;
    float4* p = (float4*)(out + ((size_t)b * TT + tt) * VV);
    float4 z = make_float4(0.f, 0.f, 0.f, 0.f);
    for (int i = threadIdx.x; i < VV / 4; i += blockDim.x) p[i] = z;
}

// ---------------- mma.sync bf16-split vocab GEMM (exact R7 version, best known) ----
// C[m,n] = sum_k A[m,k]*B[n,k]; 3-term split Ah*Bh + Al*Bh + Ah*Bl, fp32 accum.
// CTA tile 128x128, 8 warps (4m x 2n), warp tile 32x64, k-chunks of 32.
// Smem row stride 80B (5*16B): 5r mod 8 permutation -> conflict-free ldmatrix.
#define VSTRIDE 80
#define OP_BYTES (128 * VSTRIDE)   // 10240
#define SMEM_VOC (4 * OP_BYTES)    // 40960

__global__ void __launch_bounds__(256, 2)
mma_vocab(const float* __restrict__ bias, float* __restrict__ out) {
    int Mact = g_Mact;
    int m0 = blockIdx.y << 7;
    if (m0 >= Mact) return;
    int n0 = blockIdx.x << 7;

    extern __shared__ char smem[];
    const uint32_t sb = s2u(smem);
    const uint32_t sAh = sb;
    const uint32_t sAl = sb + OP_BYTES;
    const uint32_t sBh = sb + 2 * OP_BYTES;
    const uint32_t sBl = sb + 3 * OP_BYTES;

    int tid = threadIdx.x;
    int warp = tid >> 5;
    int lane = tid & 31;
    int wm = warp >> 1;  // 0..3
    int wn = warp & 1;   // 0..1

    float c[2][8][4];
#pragma unroll
    for (int mf = 0; mf < 2; ++mf)
#pragma unroll
        for (int nf = 0; nf < 8; ++nf)
#pragma unroll
            for (int q = 0; q < 4; ++q) c[mf][nf][q] = 0.f;

    // per-thread load slots: 2 x 16B units per operand per chunk
    int u0 = tid * 2;
    int lr0 = u0 >> 2, lc0 = u0 & 3;
    int lr1 = (u0 + 1) >> 2, lc1 = (u0 + 1) & 3;
    uint32_t so0 = (uint32_t)(lr0 * VSTRIDE + lc0 * 16);
    uint32_t so1 = (uint32_t)(lr1 * VSTRIDE + lc1 * 16);

    uint32_t a_off[2], b_off[4];
#pragma unroll
    for (int mf = 0; mf < 2; ++mf)
        a_off[mf] = (uint32_t)((wm * 32 + mf * 16 + (lane & 15)) * VSTRIDE + ((lane >> 4) << 4));
#pragma unroll
    for (int g = 0; g < 4; ++g)
        b_off[g] = (uint32_t)((wn * 64 + g * 16 + (lane & 15)) * VSTRIDE + ((lane >> 4) << 4));

#pragma unroll 1
    for (int ch = 0; ch < 16; ++ch) {
        int col0 = ch * 32;
        __syncthreads();
        {
            const __nv_bfloat16* pAh = g_Ahi + (size_t)m0 * HH + col0;
            const __nv_bfloat16* pAl = g_Alo + (size_t)m0 * HH + col0;
            const __nv_bfloat16* pBh = g_Bhi + (size_t)n0 * HH + col0;
            const __nv_bfloat16* pBl = g_Blo + (size_t)n0 * HH + col0;
            uint4 vah0 = *(const uint4*)(pAh + (size_t)lr0 * HH + lc0 * 8);
            uint4 vah1 = *(const uint4*)(pAh + (size_t)lr1 * HH + lc1 * 8);
            uint4 val0 = *(const uint4*)(pAl + (size_t)lr0 * HH + lc0 * 8);
            uint4 val1 = *(const uint4*)(pAl + (size_t)lr1 * HH + lc1 * 8);
            uint4 vbh0 = *(const uint4*)(pBh + (size_t)lr0 * HH + lc0 * 8);
            uint4 vbh1 = *(const uint4*)(pBh + (size_t)lr1 * HH + lc1 * 8);
            uint4 vbl0 = *(const uint4*)(pBl + (size_t)lr0 * HH + lc0 * 8);
            uint4 vbl1 = *(const uint4*)(pBl + (size_t)lr1 * HH + lc1 * 8);
            *(uint4*)(smem + (sAh - sb) + so0) = vah0;
            *(uint4*)(smem + (sAh - sb) + so1) = vah1;
            *(uint4*)(smem + (sAl - sb) + so0) = val0;
            *(uint4*)(smem + (sAl - sb) + so1) = val1;
            *(uint4*)(smem + (sBh - sb) + so0) = vbh0;
            *(uint4*)(smem + (sBh - sb) + so1) = vbh1;
            *(uint4*)(smem + (sBl - sb) + so0) = vbl0;
            *(uint4*)(smem + (sBl - sb) + so1) = vbl1;
        }
        __syncthreads();

#pragma unroll
        for (int ks = 0; ks < 2; ++ks) {
            uint32_t koff = (uint32_t)(ks * 32);
            uint32_t ah[2][4], al[2][4];
#pragma unroll
            for (int mf = 0; mf < 2; ++mf) {
                LDSM4(ah[mf], sAh + a_off[mf] + koff);
                LDSM4(al[mf], sAl + a_off[mf] + koff);
            }
#pragma unroll
            for (int g = 0; g < 4; ++g) {
                uint32_t bh[4], bl[4];
                LDSM4(bh, sBh + b_off[g] + koff);
                LDSM4(bl, sBl + b_off[g] + koff);
                // x4 frag order: r0 = n0-7/k0-7, r1 = n8-15/k0-7, r2 = n0-7/k8-15, r3 = n8-15/k8-15
#pragma unroll
                for (int mf = 0; mf < 2; ++mf) {
                    MMA16816(c[mf][2 * g + 0], ah[mf], bh[0], bh[2]);  // Ah*Bh
                    MMA16816(c[mf][2 * g + 0], al[mf], bh[0], bh[2]);  // Al*Bh
                    MMA16816(c[mf][2 * g + 0], ah[mf], bl[0], bl[2]);  // Ah*Bl
                    MMA16816(c[mf][2 * g + 1], ah[mf], bh[1], bh[3]);
                    MMA16816(c[mf][2 * g + 1], al[mf], bh[1], bh[3]);
                    MMA16816(c[mf][2 * g + 1], ah[mf], bl[1], bl[3]);
                }
            }
        }
    }

    // epilogue: frag (mf,nf): c0,c1 -> row tq, cols 2*tr+{0,1}; c2,c3 -> row tq+8
    int tq = lane >> 2;
    int tr = lane & 3;
#pragma unroll
    for (int mf = 0; mf < 2; ++mf) {
#pragma unroll
        for (int half = 0; half < 2; ++half) {
            int m = m0 + wm * 32 + mf * 16 + half * 8 + tq;
            if (m >= Mact) continue;
            size_t dst = (size_t)g_act_dst[m] * VV;
#pragma unroll
            for (int nf = 0; nf < 8; ++nf) {
                int n = n0 + wn * 64 + nf * 8 + tr * 2;
                float2 v;
                v.x = c[mf][nf][half * 2 + 0] + bias[n + 0];
                v.y = c[mf][nf][half * 2 + 1] + bias[n + 1];
                *(float2*)(out + dst + n) = v;
            }
        }
    }
}

// ---------------- launch ----------------
extern "C" void kernel_launch(void* const* d_in, const int* in_sizes, int n_in,
                              void* d_out, int out_size) {
    const float* l_total = (const float*)d_in[0];
    const int*   enc     = (const int*)d_in[1];
    const int*   capl    = (const int*)d_in[2];
    const float* emb_w   = (const float*)d_in[3];
    const float* W_ih    = (const float*)d_in[4];
    const float* W_hh    = (const float*)d_in[5];
    const float* b_ih    = (const float*)d_in[6];
    const float* b_hh    = (const float*)d_in[7];
    const float* wdc_W   = (const float*)d_in[8];
    const float* wdc_b   = (const float*)d_in[9];
    float* out = (float*)d_out;

    cudaFuncSetAttribute(lstm_persist, cudaFuncAttributeMaxDynamicSharedMemorySize, LSTM_SMEM);
    cudaFuncSetAttribute(mma_vocab, cudaFuncAttributeMaxDynamicSharedMemorySize, SMEM_VOC);

    setup_kernel<<<1, 64>>>(enc, capl, out);
    conv_wdc<<<(VV * HH / 4 + 255) / 256, 256>>>(wdc_W);
    lt_kernel<<<BB, 256>>>(l_total);
    wq_kernel<<<(HH * HH * 4 + 255) / 256, 256>>>(W_hh);
    emb_gather<<<(TT * BB * EE + 255) / 256, 256>>>(emb_w);

    gemm_kernel<0><<<dim3(G4 / 128, 1), 256>>>(W_ih, b_ih, b_hh, nullptr);
    gemm_kernel<1><<<dim3(G4 / 128, (TT * BB + 127) / 128), 256>>>(W_ih, nullptr, nullptr, nullptr);

    lstm_persist<<<64, 512, LSTM_SMEM>>>();

    conv_hid<<<(MPAD * HH / 4 + 255) / 256, 256>>>();
    zerofill<<<dim3(TT, BB), 256>>>(out);
    mma_vocab<<<dim3(VV / 128, MPAD / 128), 256, SMEM_VOC>>>(wdc_b, out);
}

// round 17
// speedup vs baseline: 2.3469x; 1.1976x over previous
#include <cuda_runtime.h>
#include <cuda_bf16.h>
#include <cstdint>
#include <math.h>

#define BB 64
#define TT 39
#define MAXLEN 40
#define FF 1024
#define EE 300
#define HH 512
#define G4 2048
#define VV 32000
#define XDIM 1324
#define MPAD 2560
#define NTILE 250
#define MTILE 20

// ---------------- scratch (static device globals; no runtime alloc) ----------------
__device__ float g_lt[BB * FF];
__device__ int   g_si[BB];
__device__ int   g_dl[BB];
__device__ int   g_caps[BB * MAXLEN];
__device__ int   g_Mact;
__device__ int   g_bar;           // LSTM progress counter (also gates GEMM tiles)
__device__ int   g_cnt[TT];
__device__ int   g_pref[TT];
__device__ int   g_act_src[TT * BB];
__device__ int   g_act_dst[TT * BB];
__device__ float g_base[BB * G4];
__device__ float g_Aemb[TT * BB * EE];
__device__ float g_gatepre[(size_t)TT * BB * G4];
__device__ float g_hall[(size_t)TT * BB * HH];
__device__ float g_Wq[HH * HH * 4];
// bf16 split operands for the tensor-core vocab GEMM
__device__ __nv_bfloat16 g_Bhi[(size_t)VV * HH];
__device__ __nv_bfloat16 g_Blo[(size_t)VV * HH];
__device__ __nv_bfloat16 g_Ahi[(size_t)MPAD * HH];
__device__ __nv_bfloat16 g_Alo[(size_t)MPAD * HH];

// ---------------- f32x2 helpers ----------------
#define FFMA2(acc, a, b) asm("fma.rn.f32x2 %0, %1, %2, %0;" : "+l"(acc) : "l"(a), "l"(b))
__device__ __forceinline__ unsigned long long PACK2(float x) {
    unsigned long long r;
    asm("mov.b64 %0, {%1, %1};" : "=l"(r) : "f"(x));
    return r;
}
__device__ __forceinline__ unsigned long long PACKF2(float lo, float hi) {
    unsigned long long r;
    asm("mov.b64 %0, {%1, %2};" : "=l"(r) : "f"(lo), "f"(hi));
    return r;
}
#define UNPACK2(lo, hi, v) asm("mov.b64 {%0, %1}, %2;" : "=f"(lo), "=f"(hi) : "l"(v))

// ---------------- baseline-PTX tensor helpers (valid on plain sm_103) ----------------
__device__ __forceinline__ uint32_t s2u(const void* p) {
    uint32_t a;
    asm("{ .reg .u64 t; cvta.to.shared.u64 t, %1; cvt.u32.u64 %0, t; }" : "=r"(a) : "l"(p));
    return a;
}

#define LDSM4(R, addr)                                                        \
    asm volatile("ldmatrix.sync.aligned.m8n8.x4.shared.b16 {%0,%1,%2,%3}, [%4];" \
                 : "=r"((R)[0]), "=r"((R)[1]), "=r"((R)[2]), "=r"((R)[3])     \
                 : "r"(addr))

#define MMA16816(C, A, B0, B1)                                                \
    asm volatile(                                                             \
        "mma.sync.aligned.m16n8k16.row.col.f32.bf16.bf16.f32 "                \
        "{%0,%1,%2,%3}, {%4,%5,%6,%7}, {%8,%9}, {%0,%1,%2,%3};"               \
        : "+f"((C)[0]), "+f"((C)[1]), "+f"((C)[2]), "+f"((C)[3])              \
        : "r"((A)[0]), "r"((A)[1]), "r"((A)[2]), "r"((A)[3]), "r"(B0), "r"(B1))

#define CP16(sdst, gsrc) \
    asm volatile("cp.async.cg.shared.global [%0], [%1], 16;" ::"r"(sdst), "l"(gsrc))
#define CP_COMMIT() asm volatile("cp.async.commit_group;" ::: "memory")
#define CP_WAIT1() asm volatile("cp.async.wait_group 1;" ::: "memory")
#define CP_WAIT0() asm volatile("cp.async.wait_group 0;" ::: "memory")

// ---------------- setup: sort, caps gather, compaction, aux outputs ----------------
__global__ void setup_kernel(const int* __restrict__ enc, const int* __restrict__ capl,
                             float* __restrict__ out) {
    __shared__ int len[BB];
    __shared__ int si[BB];
    int t = threadIdx.x;  // 64 threads
    if (t < BB) len[t] = capl[t];
    __syncthreads();
    if (t < BB) {
        int L = len[t];
        int r = 0;
        for (int j = 0; j < BB; ++j) {
            int Lj = len[j];
            if (Lj > L || (Lj == L && j < t)) r++;
        }
        si[r] = t;  // stable descending argsort
    }
    __syncthreads();
    const size_t OFF = (size_t)TT * BB * VV;
    if (t < BB) {
        int bsrc = si[t];
        g_si[t] = bsrc;
        int dl = len[bsrc] - 1;
        g_dl[t] = dl;
        for (int w = 0; w < MAXLEN; ++w) {
            int c = enc[bsrc * MAXLEN + w];
            g_caps[t * MAXLEN + w] = c;
            out[OFF + t * MAXLEN + w] = (float)c;
        }
        out[OFF + BB * MAXLEN + t] = (float)dl;
        out[OFF + BB * MAXLEN + BB + t] = (float)bsrc;
    }
    __syncthreads();
    if (t == 0) {
        g_bar = 0;  // reset progress counter every launch (graph replays!)
        int m = 0;
        for (int tt = 0; tt < TT; ++tt) {
            g_pref[tt] = m;
            int c0 = 0;
            for (int b = 0; b < BB; ++b)
                if (tt < g_dl[b]) {
                    g_act_src[m] = tt * BB + b;
                    g_act_dst[m] = b * TT + tt;
                    m++;
                    c0++;
                }
            g_cnt[tt] = c0;
        }
        g_Mact = m;
        for (int i = m; i < TT * BB; ++i) { g_act_src[i] = 0; g_act_dst[i] = 0; }
    }
}

// lt_sorted[r] = sum_s l_total[s, sort_ind[r], :]
__global__ void lt_kernel(const float* __restrict__ l_total) {
    int r = blockIdx.x;
    int bsrc = g_si[r];
    for (int f = threadIdx.x; f < FF; f += blockDim.x) {
        float s = l_total[(size_t)0 * BB * FF + bsrc * FF + f]
                + l_total[(size_t)1 * BB * FF + bsrc * FF + f]
                + l_total[(size_t)2 * BB * FF + bsrc * FF + f];
        g_lt[r * FF + f] = s;
    }
}

// Wq[(j*512 + k)*4 + g] = W_hh[(g*512 + j)*512 + k]
__global__ void wq_kernel(const float* __restrict__ W_hh) {
    int idx = blockIdx.x * blockDim.x + threadIdx.x;
    if (idx < HH * HH * 4) {
        int g = idx & 3;
        int k = (idx >> 2) & (HH - 1);
        int j = idx >> 11;
        g_Wq[idx] = W_hh[(size_t)(g * HH + j) * HH + k];
    }
}

// gather embedding rows for all (t,b)
__global__ void emb_gather(const float* __restrict__ emb_w) {
    int idx = blockIdx.x * blockDim.x + threadIdx.x;
    const int total = TT * BB * EE;
    if (idx < total) {
        int m = idx / EE;
        int k = idx - m * EE;
        int tt = m >> 6;
        int b = m & 63;
        int tok = g_caps[b * MAXLEN + tt];
        g_Aemb[idx] = emb_w[(size_t)tok * EE + k];
    }
}

// ---------------- bf16 hi/lo split conversion (B operand) ----------------
__device__ __forceinline__ void split4(float4 v, ushort4& hi, ushort4& lo) {
    __nv_bfloat16 h0 = __float2bfloat16(v.x);
    __nv_bfloat16 h1 = __float2bfloat16(v.y);
    __nv_bfloat16 h2 = __float2bfloat16(v.z);
    __nv_bfloat16 h3 = __float2bfloat16(v.w);
    __nv_bfloat16 l0 = __float2bfloat16(v.x - __bfloat162float(h0));
    __nv_bfloat16 l1 = __float2bfloat16(v.y - __bfloat162float(h1));
    __nv_bfloat16 l2 = __float2bfloat16(v.z - __bfloat162float(h2));
    __nv_bfloat16 l3 = __float2bfloat16(v.w - __bfloat162float(h3));
    hi.x = *(unsigned short*)&h0; hi.y = *(unsigned short*)&h1;
    hi.z = *(unsigned short*)&h2; hi.w = *(unsigned short*)&h3;
    lo.x = *(unsigned short*)&l0; lo.y = *(unsigned short*)&l1;
    lo.z = *(unsigned short*)&l2; lo.w = *(unsigned short*)&l3;
}

__global__ void conv_wdc(const float* __restrict__ W) {
    int i4 = blockIdx.x * blockDim.x + threadIdx.x;
    if (i4 < VV * HH / 4) {
        float4 v = ((const float4*)W)[i4];
        ushort4 hi, lo;
        split4(v, hi, lo);
        reinterpret_cast<ushort4*>(g_Bhi)[i4] = hi;
        reinterpret_cast<ushort4*>(g_Blo)[i4] = lo;
    }
}

// ---------------- SIMT SGEMM for the small pre-GEMMs (modes 0/1) ----------------
template <int MODE>
__global__ void __launch_bounds__(256, 2)
gemm_kernel(const float* __restrict__ Bm, const float* __restrict__ bias1,
            const float* __restrict__ bias2, float* __restrict__ Cout) {
    constexpr int K   = (MODE == 0) ? 1024 : 300;
    constexpr int LDA = (MODE == 0) ? 1024 : 300;
    constexpr int LDB = XDIM;
    constexpr int BC0 = (MODE == 0) ? 300 : 0;

    const float* A = (MODE == 0) ? g_lt : g_Aemb;
    int M_eff = (MODE == 0) ? 64 : (TT * BB);

    int m0 = blockIdx.y * 128;
    int n0 = blockIdx.x * 128;
    if (m0 >= M_eff) return;

    __shared__ float As[8][128];
    __shared__ float Bs[8][128];

    int tid = threadIdx.x;
    int lrow = tid & 127;
    int kq = (tid >> 7) << 2;
    int tx = tid & 15;
    int ty = tid >> 4;

    int am = min(m0 + lrow, M_eff - 1);
    const float* Ap = A + (size_t)am * LDA;
    const float* Bp = Bm + (size_t)(n0 + lrow) * LDB + BC0;

    unsigned long long acc[8][4];
#pragma unroll
    for (int i = 0; i < 8; ++i)
#pragma unroll
        for (int p = 0; p < 4; ++p) acc[i][p] = 0ull;

    const int nkt = (K + 7) >> 3;
    for (int kt = 0; kt < nkt; ++kt) {
        int kk = (kt << 3) + kq;
        float4 av, bv;
        if (kk + 3 < K) {
            av = *(const float4*)(Ap + kk);
            bv = *(const float4*)(Bp + kk);
        } else {
            av.x = (kk + 0 < K) ? Ap[kk + 0] : 0.f;
            av.y = (kk + 1 < K) ? Ap[kk + 1] : 0.f;
            av.z = (kk + 2 < K) ? Ap[kk + 2] : 0.f;
            av.w = (kk + 3 < K) ? Ap[kk + 3] : 0.f;
            bv.x = (kk + 0 < K) ? Bp[kk + 0] : 0.f;
            bv.y = (kk + 1 < K) ? Bp[kk + 1] : 0.f;
            bv.z = (kk + 2 < K) ? Bp[kk + 2] : 0.f;
            bv.w = (kk + 3 < K) ? Bp[kk + 3] : 0.f;
        }
        __syncthreads();
        As[kq + 0][lrow] = av.x; As[kq + 1][lrow] = av.y;
        As[kq + 2][lrow] = av.z; As[kq + 3][lrow] = av.w;
        Bs[kq + 0][lrow] = bv.x; Bs[kq + 1][lrow] = bv.y;
        Bs[kq + 2][lrow] = bv.z; Bs[kq + 3][lrow] = bv.w;
        __syncthreads();
#pragma unroll
        for (int k = 0; k < 8; ++k) {
            float4 a0 = *(const float4*)&As[k][ty * 8];
            float4 a1 = *(const float4*)&As[k][ty * 8 + 4];
            ulonglong2 b0 = *(const ulonglong2*)&Bs[k][tx * 8];
            ulonglong2 b1 = *(const ulonglong2*)&Bs[k][tx * 8 + 4];
            float amv[8] = {a0.x, a0.y, a0.z, a0.w, a1.x, a1.y, a1.z, a1.w};
#pragma unroll
            for (int i = 0; i < 8; ++i) {
                unsigned long long ap = PACK2(amv[i]);
                FFMA2(acc[i][0], ap, b0.x);
                FFMA2(acc[i][1], ap, b0.y);
                FFMA2(acc[i][2], ap, b1.x);
                FFMA2(acc[i][3], ap, b1.y);
            }
        }
    }

#pragma unroll
    for (int i = 0; i < 8; ++i) {
        int m = m0 + ty * 8 + i;
        if (m >= M_eff) continue;
#pragma unroll
        for (int p = 0; p < 4; ++p) {
            float lo, hi;
            UNPACK2(lo, hi, acc[i][p]);
            int n = n0 + tx * 8 + p * 2;
            if (MODE == 0) {
                g_base[(size_t)m * G4 + n + 0] = lo + bias1[n + 0] + bias2[n + 0];
                g_base[(size_t)m * G4 + n + 1] = hi + bias1[n + 1] + bias2[n + 1];
            } else {
                int b = m & 63;
                g_gatepre[(size_t)m * G4 + n + 0] = lo + g_base[(size_t)b * G4 + n + 0];
                g_gatepre[(size_t)m * G4 + n + 1] = hi + g_base[(size_t)b * G4 + n + 1];
            }
        }
    }
}

// zero masked prediction rows
__global__ void zerofill(float* __restrict__ out) {
    int tt = blockIdx.x;
    int b = blockIdx.y;
    if (tt < g_dl[b]) return;
    float4* p = (float4*)(out + ((size_t)b * TT + tt) * VV);
    float4 z = make_float4(0.f, 0.f, 0.f, 0.f);
    for (int i = threadIdx.x; i < VV / 4; i += blockDim.x) p[i] = z;
}

// ---------------- merged persistent kernel: LSTM + progress-gated vocab GEMM ------
// grid = 64 (LSTM role) + MTILE*NTILE (GEMM role), 512 threads, 199KB smem, 1 CTA/SM.
// Wave 1 (blocks 0..147) always contains all 64 LSTM CTAs -> spin-gating is safe.
// LSTM role: identical to proven lstm_persist + fused bf16 hi/lo write of h into
//   the compacted A operand rows (m = pref[t] + b), so GEMM tiles unlock per-step.
// GEMM role: 128x128 tile, 16 warps (4m x 4n, warp tile 32x32), 3-term bf16 HMMA,
//   2-stage cp.async pipeline, stride-80 conflict-free ldmatrix (proven layout).
#define LSTM_SMEM (8 * 2048 * 4 + 512 * 65 * 4)  // 198656 B (>= 2*STGB for GEMM)
#define VSTRIDE 80
#define OPB (128 * VSTRIDE)   // 10240 per operand per stage
#define STGB (4 * OPB)        // 40960 per stage

__device__ __forceinline__ void cp_stage(uint32_t sbase, int m0, int n0, int col0, int tid) {
    int r = tid >> 2;     // 0..127
    int lc = tid & 3;     // 16B unit within 64B row
    uint32_t soff = (uint32_t)(r * VSTRIDE + lc * 16);
    size_t goA = (size_t)(m0 + r) * HH + col0 + (lc << 3);
    size_t goB = (size_t)(n0 + r) * HH + col0 + (lc << 3);
    CP16(sbase + soff,           (const void*)(g_Ahi + goA));
    CP16(sbase + OPB + soff,     (const void*)(g_Alo + goA));
    CP16(sbase + 2 * OPB + soff, (const void*)(g_Bhi + goB));
    CP16(sbase + 3 * OPB + soff, (const void*)(g_Blo + goB));
    CP_COMMIT();
}

__global__ void __launch_bounds__(512, 1)
fused_lstm_gemm(const float* __restrict__ bias, float* __restrict__ out) {
    extern __shared__ float sm[];
    int tid = threadIdx.x;

    if (blockIdx.x < 64) {
        // ================= LSTM role =================
        float* Ws = sm;                 // [8 jj][512 k][4 gates]
        float* hs = sm + 8 * 2048;      // [512 k][65 b-padded]
        int b = tid & 63;
        int jj = tid >> 6;
        int j = blockIdx.x * 8 + jj;

        {
            const float4* wsrc = (const float4*)(g_Wq + (size_t)blockIdx.x * 8 * 2048);
            float4* wdst = (float4*)Ws;
            for (int i = tid; i < 8 * 2048 / 4; i += 512) wdst[i] = wsrc[i];
        }
        __syncthreads();

        const ulonglong2* W2 = (const ulonglong2*)(Ws + (size_t)jj * 2048);
        float c = 0.f;

#pragma unroll 1
        for (int t = 0; t < TT; ++t) {
            float a0, a1, a2, a3;
            {
                const float* gp = g_gatepre + ((size_t)t * BB + b) * G4 + j;
                a0 = gp[0]; a1 = gp[HH]; a2 = gp[2 * HH]; a3 = gp[3 * HH];
            }

            if (t > 0) {
                if (tid == 0) {
                    int tgt = 64 * t;
                    while (*((volatile int*)&g_bar) < tgt) __nanosleep(32);
                }
                __syncthreads();
                const float* hp = g_hall + (size_t)(t - 1) * BB * HH;
                for (int i = tid; i < BB * HH; i += 512)
                    hs[(i & 511) * 65 + (i >> 9)] = __ldcg(hp + i);
                __syncthreads();

                unsigned long long accA = PACKF2(a0, a1);
                unsigned long long accB = PACKF2(a2, a3);
#pragma unroll 8
                for (int k = 0; k < HH; ++k) {
                    unsigned long long hp2 = PACK2(hs[k * 65 + b]);
                    ulonglong2 w = W2[k];
                    FFMA2(accA, hp2, w.x);
                    FFMA2(accB, hp2, w.y);
                }
                UNPACK2(a0, a1, accA);
                UNPACK2(a2, a3, accB);
            }

            float iv = 1.f / (1.f + expf(-a0));
            float fv = 1.f / (1.f + expf(-a1));
            float gv = tanhf(a2);
            float ov = 1.f / (1.f + expf(-a3));
            c = fv * c + iv * gv;
            float h = ov * tanhf(c);
            g_hall[((size_t)t * BB + b) * HH + j] = h;

            // fused bf16 hi/lo conversion into compacted A rows
            if (b < g_cnt[t]) {
                int m = g_pref[t] + b;
                __nv_bfloat16 hb = __float2bfloat16(h);
                __nv_bfloat16 lb = __float2bfloat16(h - __bfloat162float(hb));
                g_Ahi[(size_t)m * HH + j] = hb;
                g_Alo[(size_t)m * HH + j] = lb;
            }

            __syncthreads();
            if (tid == 0) {
                __threadfence();        // release h(t) + A rows
                atomicAdd(&g_bar, 1);
            }
        }
        return;
    }

    // ================= GEMM role =================
    int q = blockIdx.x - 64;
    int m0 = (q / NTILE) << 7;   // mtile-major ascending -> early blocks need early t
    int n0 = (q % NTILE) << 7;
    int Mact = g_Mact;
    if (m0 >= Mact) return;

    // spin until all A rows of this tile are written (LSTM step tneed complete)
    {
        int last = min(m0 + 127, Mact - 1);
        int tneed = g_act_src[last] >> 6;
        int tgt = 64 * (tneed + 1);
        if (tid == 0) {
            while (*((volatile int*)&g_bar) < tgt) __nanosleep(64);
        }
        __syncthreads();
        __threadfence();  // acquire: order A reads after flag
    }

    const uint32_t sb = s2u(sm);
    int warp = tid >> 5;
    int lane = tid & 31;
    int wm = warp >> 2;  // 0..3 -> 32 m-rows
    int wn = warp & 3;   // 0..3 -> 32 n-cols

    float c[2][4][4];
#pragma unroll
    for (int mf = 0; mf < 2; ++mf)
#pragma unroll
        for (int nf = 0; nf < 4; ++nf)
#pragma unroll
            for (int p = 0; p < 4; ++p) c[mf][nf][p] = 0.f;

    uint32_t a_off[2], b_off[2];
#pragma unroll
    for (int mf = 0; mf < 2; ++mf)
        a_off[mf] = (uint32_t)((wm * 32 + mf * 16 + (lane & 15)) * VSTRIDE + ((lane >> 4) << 4));
#pragma unroll
    for (int g = 0; g < 2; ++g)
        b_off[g] = (uint32_t)((wn * 32 + g * 16 + (lane & 15)) * VSTRIDE + ((lane >> 4) << 4));

    // prime 2-stage pipeline
    cp_stage(sb, m0, n0, 0, tid);
    cp_stage(sb + STGB, m0, n0, 32, tid);

#pragma unroll 1
    for (int ch = 0; ch < 16; ++ch) {
        if (ch < 15) { CP_WAIT1(); } else { CP_WAIT0(); }
        __syncthreads();
        uint32_t s = sb + (uint32_t)(ch & 1) * STGB;
        uint32_t sAh = s, sAl = s + OPB, sBh = s + 2 * OPB, sBl = s + 3 * OPB;

#pragma unroll
        for (int ks = 0; ks < 2; ++ks) {
            uint32_t koff = (uint32_t)(ks * 32);
            uint32_t ah[2][4], al[2][4];
#pragma unroll
            for (int mf = 0; mf < 2; ++mf) {
                LDSM4(ah[mf], sAh + a_off[mf] + koff);
                LDSM4(al[mf], sAl + a_off[mf] + koff);
            }
#pragma unroll
            for (int g = 0; g < 2; ++g) {
                uint32_t bh[4], bl[4];
                LDSM4(bh, sBh + b_off[g] + koff);
                LDSM4(bl, sBl + b_off[g] + koff);
                // x4 frag order: r0=n0-7/k0-7, r1=n8-15/k0-7, r2=n0-7/k8-15, r3=n8-15/k8-15
#pragma unroll
                for (int mf = 0; mf < 2; ++mf) {
                    MMA16816(c[mf][2 * g + 0], ah[mf], bh[0], bh[2]);  // Ah*Bh
                    MMA16816(c[mf][2 * g + 0], al[mf], bh[0], bh[2]);  // Al*Bh
                    MMA16816(c[mf][2 * g + 0], ah[mf], bl[0], bl[2]);  // Ah*Bl
                    MMA16816(c[mf][2 * g + 1], ah[mf], bh[1], bh[3]);
                    MMA16816(c[mf][2 * g + 1], al[mf], bh[1], bh[3]);
                    MMA16816(c[mf][2 * g + 1], ah[mf], bl[1], bl[3]);
                }
            }
        }
        __syncthreads();
        if (ch + 2 < 16) cp_stage(sb + (uint32_t)(ch & 1) * STGB, m0, n0, (ch + 2) * 32, tid);
    }

    // epilogue: frag (mf,nf): p0,p1 -> row tq, cols 2*tr+{0,1}; p2,p3 -> row tq+8
    int tq = lane >> 2;
    int tr = lane & 3;
#pragma unroll
    for (int mf = 0; mf < 2; ++mf) {
#pragma unroll
        for (int half = 0; half < 2; ++half) {
            int m = m0 + wm * 32 + mf * 16 + half * 8 + tq;
            if (m >= Mact) continue;
            size_t dst = (size_t)g_act_dst[m] * VV;
#pragma unroll
            for (int nf = 0; nf < 4; ++nf) {
                int n = n0 + wn * 32 + nf * 8 + tr * 2;
                float2 v;
                v.x = c[mf][nf][half * 2 + 0] + bias[n + 0];
                v.y = c[mf][nf][half * 2 + 1] + bias[n + 1];
                *(float2*)(out + dst + n) = v;
            }
        }
    }
}

// ---------------- launch ----------------
extern "C" void kernel_launch(void* const* d_in, const int* in_sizes, int n_in,
                              void* d_out, int out_size) {
    const float* l_total = (const float*)d_in[0];
    const int*   enc     = (const int*)d_in[1];
    const int*   capl    = (const int*)d_in[2];
    const float* emb_w   = (const float*)d_in[3];
    const float* W_ih    = (const float*)d_in[4];
    const float* W_hh    = (const float*)d_in[5];
    const float* b_ih    = (const float*)d_in[6];
    const float* b_hh    = (const float*)d_in[7];
    const float* wdc_W   = (const float*)d_in[8];
    const float* wdc_b   = (const float*)d_in[9];
    float* out = (float*)d_out;

    cudaFuncSetAttribute(fused_lstm_gemm, cudaFuncAttributeMaxDynamicSharedMemorySize, LSTM_SMEM);

    setup_kernel<<<1, 64>>>(enc, capl, out);
    conv_wdc<<<(VV * HH / 4 + 255) / 256, 256>>>(wdc_W);
    lt_kernel<<<BB, 256>>>(l_total);
    wq_kernel<<<(HH * HH * 4 + 255) / 256, 256>>>(W_hh);
    emb_gather<<<(TT * BB * EE + 255) / 256, 256>>>(emb_w);

    gemm_kernel<0><<<dim3(G4 / 128, 1), 256>>>(W_ih, b_ih, b_hh, nullptr);
    gemm_kernel<1><<<dim3(G4 / 128, (TT * BB + 127) / 128), 256>>>(W_ih, nullptr, nullptr, nullptr);

    zerofill<<<dim3(TT, BB), 256>>>(out);
    fused_lstm_gemm<<<64 + MTILE * NTILE, 512, LSTM_SMEM>>>(wdc_b, out);
}